// round 11
// baseline (speedup 1.0000x reference)
#include <cuda_runtime.h>
#include <math.h>
#include <stdint.h>

// Problem constants
#define N_TOK 4096
#define CA 768
#define CS 384
#define CZ 128
#define NH 16
#define HD 48

#define W768 589824     // 768*768
#define W384 294912     // 384*768

// ---------------- scratch ----------------
__device__ __align__(16) float    g_sln [N_TOK * CS];
__device__ __align__(16) uint32_t g_stf [N_TOK * CS];     // tf32(s)
__device__ __align__(16) float    g_alnr[N_TOK * CA];
__device__ __align__(16) uint32_t g_alnt[N_TOK * CA];     // tf32(aln)
__device__ __align__(16) float    g_t2  [N_TOK * CA];
__device__ __align__(16) float    g_q   [N_TOK * CA];
__device__ __align__(16) float    g_k   [N_TOK * CA];
__device__ __align__(16) float    g_v   [N_TOK * CA];
__device__ __align__(16) float    g_g   [N_TOK * CA];
__device__ __align__(16) uint32_t g_t1t [N_TOK * CA];     // tf32(g*o)
__device__ __align__(16) float    g_bias[NH * 128 * 32 * 128];
__device__ __align__(16) uint32_t g_wt  [5 * W768 + W384]; // wq wk wv wg wo | wlast

// ---------------- TF32 helpers ----------------
__device__ __forceinline__ uint32_t f2tf(float x)
{
    uint32_t r;
    asm("cvt.rna.tf32.f32 %0, %1;" : "=r"(r) : "f"(x));
    return r;
}

__device__ __forceinline__ void mma8(float* c, const uint32_t* a, const uint32_t* b)
{
    asm volatile("mma.sync.aligned.m16n8k8.row.col.f32.tf32.tf32.f32 "
                 "{%0,%1,%2,%3}, {%4,%5,%6,%7}, {%8,%9}, {%0,%1,%2,%3};"
                 : "+f"(c[0]), "+f"(c[1]), "+f"(c[2]), "+f"(c[3])
                 : "r"(a[0]), "r"(a[1]), "r"(a[2]), "r"(a[3]),
                   "r"(b[0]), "r"(b[1]));
}

__device__ __forceinline__ void cp16(uint32_t dst, const void* src)
{
    asm volatile("cp.async.cg.shared.global [%0], [%1], 16;" :: "r"(dst), "l"(src));
}
#define CP_COMMIT() asm volatile("cp.async.commit_group;")
#define CP_WAIT1()  asm volatile("cp.async.wait_group 1;")

// ---------------- fused LN + weight-convert kernel ----------------
__global__ __launch_bounds__(256) void ln_fused_kernel(const float* __restrict__ s,
                                                       const float* __restrict__ gamma,
                                                       float* __restrict__ sln,
                                                       uint32_t* __restrict__ stf,
                                                       const float* __restrict__ a,
                                                       float* __restrict__ alnr,
                                                       const float* __restrict__ wq,
                                                       const float* __restrict__ wk,
                                                       const float* __restrict__ wv,
                                                       const float* __restrict__ wg,
                                                       const float* __restrict__ wo,
                                                       const float* __restrict__ wlast,
                                                       uint32_t* __restrict__ wt)
{
    int lane = threadIdx.x & 31;
    int bx = blockIdx.x;
    if (bx < 512) {
        int row = bx * 8 + (threadIdx.x >> 5);
        const float* x = s + (size_t)row * CS;
        float v[12];
        float sum = 0.f;
#pragma unroll
        for (int i = 0; i < 12; i++) { v[i] = x[lane + 32 * i]; sum += v[i]; }
#pragma unroll
        for (int o = 16; o; o >>= 1) sum += __shfl_xor_sync(0xffffffffu, sum, o);
        float m = sum * (1.0f / CS);
        float ss = 0.f;
#pragma unroll
        for (int i = 0; i < 12; i++) { float d = v[i] - m; ss += d * d; }
#pragma unroll
        for (int o = 16; o; o >>= 1) ss += __shfl_xor_sync(0xffffffffu, ss, o);
        float inv = rsqrtf(ss * (1.0f / CS) + 1e-5f);
        float* op = sln + (size_t)row * CS;
        uint32_t* op2 = stf + (size_t)row * CS;
#pragma unroll
        for (int i = 0; i < 12; i++) {
            op [lane + 32 * i] = (v[i] - m) * inv * gamma[lane + 32 * i];
            op2[lane + 32 * i] = f2tf(v[i]);
        }
    } else if (bx < 1024) {
        int row = (bx - 512) * 8 + (threadIdx.x >> 5);
        const float* x = a + (size_t)row * CA;
        float v[24];
        float sum = 0.f;
#pragma unroll
        for (int i = 0; i < 24; i++) { v[i] = x[lane + 32 * i]; sum += v[i]; }
#pragma unroll
        for (int o = 16; o; o >>= 1) sum += __shfl_xor_sync(0xffffffffu, sum, o);
        float m = sum * (1.0f / CA);
        float ss = 0.f;
#pragma unroll
        for (int i = 0; i < 24; i++) { float d = v[i] - m; ss += d * d; }
#pragma unroll
        for (int o = 16; o; o >>= 1) ss += __shfl_xor_sync(0xffffffffu, ss, o);
        float inv = rsqrtf(ss * (1.0f / CA) + 1e-5f);
        float* op = alnr + (size_t)row * CA;
#pragma unroll
        for (int i = 0; i < 24; i++)
            op[lane + 32 * i] = (v[i] - m) * inv;
    } else {
        int b = bx - 1024;
        const float* src;
        uint32_t* dst;
        int local;
        if (b < 2880) {
            int seg = b / 576;
            local = b - seg * 576;
            src = (seg == 0) ? wq : (seg == 1) ? wk : (seg == 2) ? wv
                : (seg == 3) ? wg : wo;
            dst = wt + (size_t)seg * W768;
        } else {
            local = b - 2880;
            src = wlast;
            dst = wt + (size_t)5 * W768;
        }
        int idx = local * 256 + threadIdx.x;
        float4 vsrc = ((const float4*)src)[idx];
        uint4 vd;
        vd.x = f2tf(vsrc.x); vd.y = f2tf(vsrc.y);
        vd.z = f2tf(vsrc.z); vd.w = f2tf(vsrc.w);
        ((uint4*)dst)[idx] = vd;
    }
}

// ---------------- cp.async TF32 GEMM: BM=128 BN=128 BK=16, 3 stages ----------------
#define ASTRIDE 20
#define STAGE_WORDS (128 * ASTRIDE + 16 * 136)   // 4736
#define GEMM_SMEM (3 * STAGE_WORDS * 4)          // 56832 B

__device__ __forceinline__ void issue_tile(uint32_t sbase,
                                           const uint32_t* __restrict__ A,
                                           const uint32_t* __restrict__ B,
                                           int K, int k0, int row0, int col0, int tid)
{
    int arow = tid >> 1, ac = (tid & 1) * 2;
    const uint32_t* asrc = A + (size_t)(row0 + arow) * K + k0 + ac * 4;
    uint32_t adst = sbase + (arow * ASTRIDE + ac * 4) * 4;
    cp16(adst, asrc);
    cp16(adst + 16, asrc + 4);
    int brow = tid >> 4, bc = (tid & 15) * 2;
    const uint32_t* bsrc = B + (size_t)(k0 + brow) * 768 + col0 + bc * 4;
    uint32_t bdst = sbase + (128 * ASTRIDE + brow * 136 + bc * 4) * 4;
    cp16(bdst, bsrc);
    cp16(bdst + 16, bsrc + 4);
}

__device__ __forceinline__ void gemm_ca_body(const uint32_t* __restrict__ A,
                                             const uint32_t* __restrict__ B,
                                             const float* __restrict__ bias,
                                             const float* __restrict__ emul,
                                             float* __restrict__ C,
                                             int K, int act, int bx, int by)
{
    extern __shared__ uint32_t gsm[];
    uint32_t sbase = (uint32_t)__cvta_generic_to_shared(gsm);

    int tid = threadIdx.x;
    int wid = tid >> 5, lane = tid & 31;
    int warp_m = wid >> 2, warp_n = wid & 3;
    int group = lane >> 2, tg = lane & 3;
    int row0 = by * 128;
    int col0 = bx * 128;

    float acc[4][4][4];
#pragma unroll
    for (int mt = 0; mt < 4; mt++)
#pragma unroll
        for (int nt = 0; nt < 4; nt++)
#pragma unroll
            for (int r = 0; r < 4; r++) acc[mt][nt][r] = 0.f;

    int kt = K >> 4;
    issue_tile(sbase, A, B, K, 0, row0, col0, tid);
    CP_COMMIT();
    issue_tile(sbase + STAGE_WORDS * 4, A, B, K, 16, row0, col0, tid);
    CP_COMMIT();

    int stage = 0;
    for (int it = 0; it < kt; it++) {
        CP_WAIT1();
        __syncthreads();
        const uint32_t* As = gsm + stage * STAGE_WORDS;
        const uint32_t* Bs = As + 128 * ASTRIDE;

#pragma unroll
        for (int kc = 0; kc < 2; kc++) {
            int kb = kc * 8;
            uint32_t afr[4][4];
#pragma unroll
            for (int mt = 0; mt < 4; mt++) {
                int m = (warp_m * 64 + mt * 16 + group) * ASTRIDE;
                afr[mt][0] = As[m + kb + tg];
                afr[mt][1] = As[m + 8 * ASTRIDE + kb + tg];
                afr[mt][2] = As[m + kb + tg + 4];
                afr[mt][3] = As[m + 8 * ASTRIDE + kb + tg + 4];
            }
            uint32_t bfr[4][2];
#pragma unroll
            for (int nt = 0; nt < 4; nt++) {
                int n = warp_n * 32 + nt * 8 + group;
                bfr[nt][0] = Bs[(kb + tg) * 136 + n];
                bfr[nt][1] = Bs[(kb + tg + 4) * 136 + n];
            }
#pragma unroll
            for (int mt = 0; mt < 4; mt++)
#pragma unroll
                for (int nt = 0; nt < 4; nt++)
                    mma8(acc[mt][nt], afr[mt], bfr[nt]);
        }

        if (it + 2 < kt) {
            int nst = stage + 2; if (nst >= 3) nst -= 3;
            issue_tile(sbase + nst * STAGE_WORDS * 4, A, B, K,
                       (it + 2) * 16, row0, col0, tid);
        }
        CP_COMMIT();
        stage = stage + 1; if (stage == 3) stage = 0;
    }

#pragma unroll
    for (int mt = 0; mt < 4; mt++) {
#pragma unroll
        for (int nt = 0; nt < 4; nt++) {
            int col = col0 + warp_n * 32 + nt * 8 + tg * 2;
            float b0 = bias ? bias[col]     : 0.f;
            float b1 = bias ? bias[col + 1] : 0.f;
#pragma unroll
            for (int half = 0; half < 2; half++) {
                int row = row0 + warp_m * 64 + mt * 16 + group + half * 8;
                float v0 = acc[mt][nt][half * 2 + 0] + b0;
                float v1 = acc[mt][nt][half * 2 + 1] + b1;
                if (act == 1) {
                    v0 = 1.f / (1.f + expf(-v0));
                    v1 = 1.f / (1.f + expf(-v1));
                }
                if (emul) {
                    v0 *= emul[(size_t)row * 768 + col];
                    v1 *= emul[(size_t)row * 768 + col + 1];
                }
                float2 r = make_float2(v0, v1);
                *(float2*)&C[(size_t)row * 768 + col] = r;
            }
        }
    }
}

__global__ __launch_bounds__(256, 3) void tgemm_ca(const uint32_t* __restrict__ A,
                                                   const uint32_t* __restrict__ B,
                                                   const float* __restrict__ bias,
                                                   const float* __restrict__ emul,
                                                   float* __restrict__ C,
                                                   int K, int act)
{
    gemm_ca_body(A, B, bias, emul, C, K, act, blockIdx.x, blockIdx.y);
}

__global__ __launch_bounds__(256, 3) void tgemm_qkvg_ca(const uint32_t* __restrict__ alnt,
                                                        const uint32_t* __restrict__ wt,
                                                        const float* __restrict__ bq,
                                                        const float* __restrict__ bg,
                                                        float* __restrict__ q,
                                                        float* __restrict__ k,
                                                        float* __restrict__ v,
                                                        float* __restrict__ g)
{
    int zi = blockIdx.z;
    const uint32_t* B = wt + (size_t)zi * W768;
    const float* bias = (zi == 0) ? bq : (zi == 3) ? bg : nullptr;
    float* C          = (zi == 0) ? q  : (zi == 1) ? k  : (zi == 2) ? v  : g;
    int act           = (zi == 3) ? 1 : 0;
    gemm_ca_body(alnt, B, bias, nullptr, C, 768, act, blockIdx.x, blockIdx.y);
}

// ---------------- dual-B adaln GEMM (BN=64, writes tf32 aln) ----------------
#define AS_STRIDE 136
#define BS_STRIDE 72
__global__ __launch_bounds__(256) void adaln_kernel(const float* __restrict__ sln,
                                                    const float* __restrict__ ws,
                                                    const float* __restrict__ wskip,
                                                    const float* __restrict__ bs,
                                                    const float* __restrict__ alnr,
                                                    uint32_t* __restrict__ alnt)
{
    __shared__ uint32_t As [16 * AS_STRIDE];
    __shared__ uint32_t Bs1[16 * BS_STRIDE];
    __shared__ uint32_t Bs2[16 * BS_STRIDE];

    const int K = 384;
    int tid = threadIdx.x;
    int wid = tid >> 5, lane = tid & 31;
    int warp_m = wid >> 1, warp_n = wid & 1;
    int group = lane >> 2, tg = lane & 3;
    int row0 = blockIdx.y * 128;
    int col0 = blockIdx.x * 64;

    int arow = tid >> 1, akp = (tid & 1) * 8;
    int brow = tid >> 4, bcol = (tid & 15) * 4;

    const float* Abase = sln + (size_t)(row0 + arow) * K;

    float acc1[2][4][4], acc2[2][4][4];
#pragma unroll
    for (int mt = 0; mt < 2; mt++)
#pragma unroll
        for (int nt = 0; nt < 4; nt++)
#pragma unroll
            for (int r = 0; r < 4; r++) { acc1[mt][nt][r] = 0.f; acc2[mt][nt][r] = 0.f; }

    {
        float4 va0 = *(const float4*)(Abase + akp);
        float4 va1 = *(const float4*)(Abase + akp + 4);
        float4 vb1 = *(const float4*)(ws    + (size_t)brow * 768 + col0 + bcol);
        float4 vb2 = *(const float4*)(wskip + (size_t)brow * 768 + col0 + bcol);
        float av[8] = {va0.x, va0.y, va0.z, va0.w, va1.x, va1.y, va1.z, va1.w};
#pragma unroll
        for (int i = 0; i < 8; i++) As[(akp + i) * AS_STRIDE + arow] = f2tf(av[i]);
        float b1v[4] = {vb1.x, vb1.y, vb1.z, vb1.w};
        float b2v[4] = {vb2.x, vb2.y, vb2.z, vb2.w};
#pragma unroll
        for (int i = 0; i < 4; i++) {
            Bs1[brow * BS_STRIDE + bcol + i] = f2tf(b1v[i]);
            Bs2[brow * BS_STRIDE + bcol + i] = f2tf(b2v[i]);
        }
    }

    for (int k0 = 0; k0 < K; k0 += 16) {
        __syncthreads();
        bool has_next = (k0 + 16) < K;
        float4 va0, va1, vb1, vb2;
        if (has_next) {
            va0 = *(const float4*)(Abase + k0 + 16 + akp);
            va1 = *(const float4*)(Abase + k0 + 16 + akp + 4);
            vb1 = *(const float4*)(ws    + (size_t)(k0 + 16 + brow) * 768 + col0 + bcol);
            vb2 = *(const float4*)(wskip + (size_t)(k0 + 16 + brow) * 768 + col0 + bcol);
        }

#pragma unroll
        for (int kc = 0; kc < 2; kc++) {
            int kb = kc * 8;
            uint32_t afr[2][4];
#pragma unroll
            for (int mt = 0; mt < 2; mt++) {
                int m = warp_m * 32 + mt * 16 + group;
                afr[mt][0] = As[(kb + tg) * AS_STRIDE + m];
                afr[mt][1] = As[(kb + tg) * AS_STRIDE + m + 8];
                afr[mt][2] = As[(kb + tg + 4) * AS_STRIDE + m];
                afr[mt][3] = As[(kb + tg + 4) * AS_STRIDE + m + 8];
            }
#pragma unroll
            for (int nt = 0; nt < 4; nt++) {
                int n = warp_n * 32 + nt * 8 + group;
                uint32_t b1[2], b2[2];
                b1[0] = Bs1[(kb + tg) * BS_STRIDE + n];
                b1[1] = Bs1[(kb + tg + 4) * BS_STRIDE + n];
                b2[0] = Bs2[(kb + tg) * BS_STRIDE + n];
                b2[1] = Bs2[(kb + tg + 4) * BS_STRIDE + n];
#pragma unroll
                for (int mt = 0; mt < 2; mt++) {
                    mma8(acc1[mt][nt], afr[mt], b1);
                    mma8(acc2[mt][nt], afr[mt], b2);
                }
            }
        }

        __syncthreads();
        if (has_next) {
            float av[8] = {va0.x, va0.y, va0.z, va0.w, va1.x, va1.y, va1.z, va1.w};
#pragma unroll
            for (int i = 0; i < 8; i++) As[(akp + i) * AS_STRIDE + arow] = f2tf(av[i]);
            float b1v[4] = {vb1.x, vb1.y, vb1.z, vb1.w};
            float b2v[4] = {vb2.x, vb2.y, vb2.z, vb2.w};
#pragma unroll
            for (int i = 0; i < 4; i++) {
                Bs1[brow * BS_STRIDE + bcol + i] = f2tf(b1v[i]);
                Bs2[brow * BS_STRIDE + bcol + i] = f2tf(b2v[i]);
            }
        }
    }

#pragma unroll
    for (int mt = 0; mt < 2; mt++) {
#pragma unroll
        for (int nt = 0; nt < 4; nt++) {
            int col = col0 + warp_n * 32 + nt * 8 + tg * 2;
            float b0 = bs[col], b1 = bs[col + 1];
#pragma unroll
            for (int half = 0; half < 2; half++) {
                int row = row0 + warp_m * 32 + mt * 16 + group + half * 8;
                float s0 = 1.f / (1.f + expf(-(acc1[mt][nt][half * 2 + 0] + b0)));
                float s1 = 1.f / (1.f + expf(-(acc1[mt][nt][half * 2 + 1] + b1)));
                float r0 = s0 * alnr[(size_t)row * 768 + col]     + acc2[mt][nt][half * 2 + 0];
                float r1 = s1 * alnr[(size_t)row * 768 + col + 1] + acc2[mt][nt][half * 2 + 1];
                uint2 rr;
                rr.x = f2tf(r0);
                rr.y = f2tf(r1);
                *(uint2*)&alnt[(size_t)row * 768 + col] = rr;
            }
        }
    }
}

// ---------------- bias = LN(z)*gamma @ wz (fused LN + TF32 GEMM) ----------------
#define ZAS 132
#define ZBS 24
#define BIAS2_SMEM ((128 * ZAS + 128 * ZBS) * 4)
__global__ __launch_bounds__(256, 2) void bias2_kernel(const float* __restrict__ z,
                                                       const float* __restrict__ gamma,
                                                       const float* __restrict__ wz,
                                                       float* __restrict__ out)
{
    extern __shared__ uint32_t dyn[];
    uint32_t* As = dyn;
    uint32_t* Bs = dyn + 128 * ZAS;
    float*    st = (float*)dyn;

    int tid = threadIdx.x;
    int wid = tid >> 5, lane = tid & 31;
    int blk = blockIdx.x;

    for (int idx = tid; idx < 2048; idx += 256) {
        int c = idx >> 4, h = idx & 15;
        Bs[c * ZBS + h] = f2tf(wz[idx]);
    }

    float4 g4 = *(const float4*)(gamma + lane * 4);

    const float* zbase = z + ((size_t)blk * 128 + wid) * CZ + lane * 4;
    float4 rv[16];
#pragma unroll
    for (int i = 0; i < 16; i++)
        rv[i] = *(const float4*)(zbase + (size_t)i * 8 * CZ);

#pragma unroll
    for (int i = 0; i < 16; i++) {
        int r = wid + 8 * i;
        float4 x = rv[i];
        float sum = x.x + x.y + x.z + x.w;
#pragma unroll
        for (int o = 16; o; o >>= 1) sum += __shfl_xor_sync(0xffffffffu, sum, o);
        float m = sum * (1.0f / CZ);
        float d0 = x.x - m, d1 = x.y - m, d2 = x.z - m, d3 = x.w - m;
        float ss = d0 * d0 + d1 * d1 + d2 * d2 + d3 * d3;
#pragma unroll
        for (int o = 16; o; o >>= 1) ss += __shfl_xor_sync(0xffffffffu, ss, o);
        float inv = rsqrtf(ss * (1.0f / CZ) + 1e-5f);
        uint4 pk;
        pk.x = f2tf(d0 * inv * g4.x);
        pk.y = f2tf(d1 * inv * g4.y);
        pk.z = f2tf(d2 * inv * g4.z);
        pk.w = f2tf(d3 * inv * g4.w);
        *(uint4*)&As[r * ZAS + lane * 4] = pk;
    }
    __syncthreads();

    int group = lane >> 2, tg = lane & 3;
    int m0 = wid * 16;
    float acc[2][4];
#pragma unroll
    for (int nt = 0; nt < 2; nt++)
#pragma unroll
        for (int r = 0; r < 4; r++) acc[nt][r] = 0.f;

#pragma unroll
    for (int ks = 0; ks < 16; ks++) {
        int kb = ks * 8;
        uint32_t a[4];
        a[0] = As[(m0 + group)     * ZAS + kb + tg];
        a[1] = As[(m0 + group + 8) * ZAS + kb + tg];
        a[2] = As[(m0 + group)     * ZAS + kb + tg + 4];
        a[3] = As[(m0 + group + 8) * ZAS + kb + tg + 4];
        uint32_t b0[2], b1[2];
        b0[0] = Bs[(kb + tg)     * ZBS + group];
        b0[1] = Bs[(kb + tg + 4) * ZBS + group];
        b1[0] = Bs[(kb + tg)     * ZBS + 8 + group];
        b1[1] = Bs[(kb + tg + 4) * ZBS + 8 + group];
        mma8(acc[0], a, b0);
        mma8(acc[1], a, b1);
    }
    __syncthreads();

#pragma unroll
    for (int nt = 0; nt < 2; nt++)
#pragma unroll
        for (int half = 0; half < 2; half++) {
            int m  = m0 + group + half * 8;
            int h0 = nt * 8 + tg * 2;
            st[h0       * 129 + m] = acc[nt][half * 2 + 0];
            st[(h0 + 1) * 129 + m] = acc[nt][half * 2 + 1];
        }
    __syncthreads();

    int wwin = blk >> 5;
    int rembase = (blk & 31) * 128;
#pragma unroll
    for (int i = 0; i < 8; i++) {
        int idx = tid + 256 * i;
        int h = idx >> 7, m = idx & 127;
        out[((size_t)(wwin * 16 + h)) * 4096 + rembase + m] = st[h * 129 + m];
    }
}

// ---------------- local attention (lean) -> writes tf32(g * o) ----------------
#define ATTN_SMEM ((32 * 48 + 2 * 128 * 52) * 4)
__global__ __launch_bounds__(256, 3) void attn_kernel(const float* __restrict__ q,
                                                      const float* __restrict__ k,
                                                      const float* __restrict__ v,
                                                      const float* __restrict__ bias,
                                                      const float* __restrict__ gate,
                                                      uint32_t* __restrict__ t1)
{
    extern __shared__ float sm[];
    float* qs = sm;
    float* ks = sm + 32 * 48;
    float* vs = ks + 128 * 52;
    int w = blockIdx.x, h = blockIdx.y;
    int tid = threadIdx.x;

    {
        const float* qbase = q + (size_t)w * 32 * CA + h * 48;
#pragma unroll
        for (int it = 0; it < 2; it++) {
            int i = tid + it * 256;
            if (i < 384) {
                int r = i / 12, c = i - r * 12;
                *(float4*)&qs[r * 48 + c * 4] =
                    *(const float4*)(qbase + (size_t)r * CA + c * 4);
            }
        }
    }
    {
        int r = tid >> 1, half = tid & 1;
        int tok = w * 32 - 48 + r;
        tok = tok < 0 ? 0 : (tok > 4095 ? 4095 : tok);
        const float4* kg = (const float4*)(k + (size_t)tok * CA + h * 48) + half * 6;
        const float4* vg = (const float4*)(v + (size_t)tok * CA + h * 48) + half * 6;
        float* kd = &ks[r * 52 + half * 24];
        float* vd = &vs[r * 52 + half * 24];
#pragma unroll
        for (int j = 0; j < 6; j++) {
            *(float4*)&kd[j * 4] = kg[j];
            *(float4*)&vd[j * 4] = vg[j];
        }
    }
    __syncthreads();

    int qi = tid >> 3, g = tid & 7;
    float4 qreg[12];
#pragma unroll
    for (int j = 0; j < 12; j++) qreg[j] = *(const float4*)&qs[qi * 48 + 4 * j];

    const float scale = 0.14433756729740643f;
    float sc[16];
    const float* bp = bias + ((size_t)(w * 16 + h) * 32 + qi) * 128;
#pragma unroll
    for (int jj = 0; jj < 16; jj++) {
        int kj = g + 8 * jj;
        int tok = w * 32 - 48 + kj;
        if (tok < 0 || tok >= 4096) { sc[jj] = -1e9f; continue; }
        const float4* kp = (const float4*)&ks[kj * 52];
        float a0 = 0.f, a1 = 0.f, a2 = 0.f, a3 = 0.f;
#pragma unroll
        for (int j = 0; j < 12; j++) {
            float4 kv = kp[j];
            a0 += qreg[j].x * kv.x;
            a1 += qreg[j].y * kv.y;
            a2 += qreg[j].z * kv.z;
            a3 += qreg[j].w * kv.w;
        }
        sc[jj] = ((a0 + a1) + (a2 + a3)) * scale + bp[kj];
    }
    float mx = sc[0];
#pragma unroll
    for (int jj = 1; jj < 16; jj++) mx = fmaxf(mx, sc[jj]);
#pragma unroll
    for (int o2 = 1; o2 < 8; o2 <<= 1) mx = fmaxf(mx, __shfl_xor_sync(0xffffffffu, mx, o2));
    float sum = 0.f;
#pragma unroll
    for (int jj = 0; jj < 16; jj++) { sc[jj] = __expf(sc[jj] - mx); sum += sc[jj]; }
#pragma unroll
    for (int o2 = 1; o2 < 8; o2 <<= 1) sum += __shfl_xor_sync(0xffffffffu, sum, o2);
    float inv = 1.f / sum;

    float oa[48];
#pragma unroll
    for (int d = 0; d < 48; d++) oa[d] = 0.f;
#pragma unroll
    for (int jj = 0; jj < 16; jj++) {
        float p = sc[jj] * inv;
        const float4* vp = (const float4*)&vs[(g + 8 * jj) * 52];
#pragma unroll
        for (int j = 0; j < 12; j++) {
            float4 vv = vp[j];
            oa[4 * j + 0] += p * vv.x; oa[4 * j + 1] += p * vv.y;
            oa[4 * j + 2] += p * vv.z; oa[4 * j + 3] += p * vv.w;
        }
    }
#pragma unroll
    for (int o2 = 1; o2 < 8; o2 <<= 1)
#pragma unroll
        for (int d = 0; d < 48; d++)
            oa[d] += __shfl_xor_sync(0xffffffffu, oa[d], o2);

    size_t rowbase = (size_t)(w * 32 + qi) * CA + h * 48;
#pragma unroll
    for (int j = 0; j < 6; j++) {
        int d = g * 6 + j;
        float gv = gate[rowbase + d];
        t1[rowbase + d] = f2tf(gv * oa[d]);
    }
}

// ---------------- launch ----------------
extern "C" void kernel_launch(void* const* d_in, const int* in_sizes, int n_in,
                              void* d_out, int out_size)
{
    const float* a        = (const float*)d_in[0];
    const float* s        = (const float*)d_in[1];
    const float* z        = (const float*)d_in[2];
    const float* gamma_s  = (const float*)d_in[3];
    const float* ws       = (const float*)d_in[4];
    const float* bs       = (const float*)d_in[5];
    const float* wskip    = (const float*)d_in[6];
    const float* lnzg     = (const float*)d_in[7];
    const float* wz       = (const float*)d_in[8];
    const float* wq       = (const float*)d_in[9];
    const float* bq       = (const float*)d_in[10];
    const float* wk       = (const float*)d_in[11];
    const float* wv       = (const float*)d_in[12];
    const float* wg       = (const float*)d_in[13];
    const float* bg       = (const float*)d_in[14];
    const float* wo       = (const float*)d_in[15];
    const float* bo       = (const float*)d_in[16];
    const float* wlast    = (const float*)d_in[17];
    const float* blast    = (const float*)d_in[18];
    float* out = (float*)d_out;

    float *p_sln, *p_alnr, *p_t2, *p_q, *p_k, *p_v, *p_g, *p_bias;
    uint32_t *p_stf, *p_alnt, *p_t1t, *p_wt;
    cudaGetSymbolAddress((void**)&p_sln,  g_sln);
    cudaGetSymbolAddress((void**)&p_stf,  g_stf);
    cudaGetSymbolAddress((void**)&p_alnr, g_alnr);
    cudaGetSymbolAddress((void**)&p_alnt, g_alnt);
    cudaGetSymbolAddress((void**)&p_t2,   g_t2);
    cudaGetSymbolAddress((void**)&p_q,    g_q);
    cudaGetSymbolAddress((void**)&p_k,    g_k);
    cudaGetSymbolAddress((void**)&p_v,    g_v);
    cudaGetSymbolAddress((void**)&p_g,    g_g);
    cudaGetSymbolAddress((void**)&p_t1t,  g_t1t);
    cudaGetSymbolAddress((void**)&p_bias, g_bias);
    cudaGetSymbolAddress((void**)&p_wt,   g_wt);

    cudaFuncSetAttribute(attn_kernel,   cudaFuncAttributeMaxDynamicSharedMemorySize, ATTN_SMEM);
    cudaFuncSetAttribute(bias2_kernel,  cudaFuncAttributeMaxDynamicSharedMemorySize, BIAS2_SMEM);
    cudaFuncSetAttribute(tgemm_ca,      cudaFuncAttributeMaxDynamicSharedMemorySize, GEMM_SMEM);
    cudaFuncSetAttribute(tgemm_qkvg_ca, cudaFuncAttributeMaxDynamicSharedMemorySize, GEMM_SMEM);

    // 0: LN(s)+stf / LN(a) / weight tf32 conversion — all independent
    ln_fused_kernel<<<4192, 256>>>(s, gamma_s, p_sln, p_stf, a, p_alnr,
                                   wq, wk, wv, wg, wo, wlast, p_wt);

    // 1: aln = sigmoid(sln@ws + bs) * ln(a) + sln@wskip  (writes tf32 aln)
    adaln_kernel<<<dim3(12, 32), 256>>>(p_sln, ws, wskip, bs, p_alnr, p_alnt);

    // 2: pair-bias
    bias2_kernel<<<4096, 256, BIAS2_SMEM>>>(z, lnzg, wz, p_bias);

    // 3: Q/K/V/G projections (cp.async)
    tgemm_qkvg_ca<<<dim3(6, 32, 4), 256, GEMM_SMEM>>>(p_alnt, p_wt, bq, bg,
                                                      p_q, p_k, p_v, p_g);

    // 4: attention -> t1 = tf32(g * o)
    attn_kernel<<<dim3(128, 16), 256, ATTN_SMEM>>>(p_q, p_k, p_v, p_bias, p_g, p_t1t);

    // 5: t2 = t1 @ wo + bo
    tgemm_ca<<<dim3(6, 32), 256, GEMM_SMEM>>>(p_t1t, p_wt + (size_t)4 * W768,
                                              bo, nullptr, p_t2, 768, 0);
    // 6: out = sigmoid(s @ wlast + blast) * t2
    tgemm_ca<<<dim3(6, 32), 256, GEMM_SMEM>>>(p_stf, p_wt + (size_t)5 * W768,
                                              blast, p_t2, out, 384, 1);
}

// round 12
// speedup vs baseline: 1.0456x; 1.0456x over previous
#include <cuda_runtime.h>
#include <math.h>
#include <stdint.h>

// Problem constants
#define N_TOK 4096
#define CA 768
#define CS 384
#define CZ 128
#define NH 16
#define HD 48

#define W768 589824     // 768*768
#define W384 294912     // 384*768

// ---------------- scratch ----------------
__device__ __align__(16) float    g_sln [N_TOK * CS];
__device__ __align__(16) uint32_t g_stf [N_TOK * CS];     // tf32(s)
__device__ __align__(16) float    g_alnr[N_TOK * CA];
__device__ __align__(16) uint32_t g_alnt[N_TOK * CA];     // tf32(aln)
__device__ __align__(16) float    g_t2  [N_TOK * CA];
__device__ __align__(16) float    g_q   [N_TOK * CA];
__device__ __align__(16) float    g_k   [N_TOK * CA];
__device__ __align__(16) float    g_v   [N_TOK * CA];
__device__ __align__(16) float    g_g   [N_TOK * CA];
__device__ __align__(16) uint32_t g_t1t [N_TOK * CA];     // tf32(g*o)
__device__ __align__(16) float    g_bias[NH * 128 * 32 * 128];
__device__ __align__(16) uint32_t g_wt  [5 * W768 + W384]; // wq wk wv wg wo | wlast

// ---------------- TF32 helpers ----------------
__device__ __forceinline__ uint32_t f2tf(float x)
{
    uint32_t r;
    asm("cvt.rna.tf32.f32 %0, %1;" : "=r"(r) : "f"(x));
    return r;
}

__device__ __forceinline__ void mma8(float* c, const uint32_t* a, const uint32_t* b)
{
    asm volatile("mma.sync.aligned.m16n8k8.row.col.f32.tf32.tf32.f32 "
                 "{%0,%1,%2,%3}, {%4,%5,%6,%7}, {%8,%9}, {%0,%1,%2,%3};"
                 : "+f"(c[0]), "+f"(c[1]), "+f"(c[2]), "+f"(c[3])
                 : "r"(a[0]), "r"(a[1]), "r"(a[2]), "r"(a[3]),
                   "r"(b[0]), "r"(b[1]));
}

__device__ __forceinline__ void cp16(uint32_t dst, const void* src)
{
    asm volatile("cp.async.cg.shared.global [%0], [%1], 16;" :: "r"(dst), "l"(src));
}
#define CP_COMMIT() asm volatile("cp.async.commit_group;")
#define CP_WAIT1()  asm volatile("cp.async.wait_group 1;")

// ---------------- fused LN + weight-convert kernel ----------------
__global__ __launch_bounds__(256) void ln_fused_kernel(const float* __restrict__ s,
                                                       const float* __restrict__ gamma,
                                                       float* __restrict__ sln,
                                                       uint32_t* __restrict__ stf,
                                                       const float* __restrict__ a,
                                                       float* __restrict__ alnr,
                                                       const float* __restrict__ wq,
                                                       const float* __restrict__ wk,
                                                       const float* __restrict__ wv,
                                                       const float* __restrict__ wg,
                                                       const float* __restrict__ wo,
                                                       const float* __restrict__ wlast,
                                                       uint32_t* __restrict__ wt)
{
    int lane = threadIdx.x & 31;
    int bx = blockIdx.x;
    if (bx < 512) {
        int row = bx * 8 + (threadIdx.x >> 5);
        const float* x = s + (size_t)row * CS;
        float v[12];
        float sum = 0.f;
#pragma unroll
        for (int i = 0; i < 12; i++) { v[i] = x[lane + 32 * i]; sum += v[i]; }
#pragma unroll
        for (int o = 16; o; o >>= 1) sum += __shfl_xor_sync(0xffffffffu, sum, o);
        float m = sum * (1.0f / CS);
        float ss = 0.f;
#pragma unroll
        for (int i = 0; i < 12; i++) { float d = v[i] - m; ss += d * d; }
#pragma unroll
        for (int o = 16; o; o >>= 1) ss += __shfl_xor_sync(0xffffffffu, ss, o);
        float inv = rsqrtf(ss * (1.0f / CS) + 1e-5f);
        float* op = sln + (size_t)row * CS;
        uint32_t* op2 = stf + (size_t)row * CS;
#pragma unroll
        for (int i = 0; i < 12; i++) {
            op [lane + 32 * i] = (v[i] - m) * inv * gamma[lane + 32 * i];
            op2[lane + 32 * i] = f2tf(v[i]);
        }
    } else if (bx < 1024) {
        int row = (bx - 512) * 8 + (threadIdx.x >> 5);
        const float* x = a + (size_t)row * CA;
        float v[24];
        float sum = 0.f;
#pragma unroll
        for (int i = 0; i < 24; i++) { v[i] = x[lane + 32 * i]; sum += v[i]; }
#pragma unroll
        for (int o = 16; o; o >>= 1) sum += __shfl_xor_sync(0xffffffffu, sum, o);
        float m = sum * (1.0f / CA);
        float ss = 0.f;
#pragma unroll
        for (int i = 0; i < 24; i++) { float d = v[i] - m; ss += d * d; }
#pragma unroll
        for (int o = 16; o; o >>= 1) ss += __shfl_xor_sync(0xffffffffu, ss, o);
        float inv = rsqrtf(ss * (1.0f / CA) + 1e-5f);
        float* op = alnr + (size_t)row * CA;
#pragma unroll
        for (int i = 0; i < 24; i++)
            op[lane + 32 * i] = (v[i] - m) * inv;
    } else {
        int b = bx - 1024;
        const float* src;
        uint32_t* dst;
        int local;
        if (b < 2880) {
            int seg = b / 576;
            local = b - seg * 576;
            src = (seg == 0) ? wq : (seg == 1) ? wk : (seg == 2) ? wv
                : (seg == 3) ? wg : wo;
            dst = wt + (size_t)seg * W768;
        } else {
            local = b - 2880;
            src = wlast;
            dst = wt + (size_t)5 * W768;
        }
        int idx = local * 256 + threadIdx.x;
        float4 vsrc = ((const float4*)src)[idx];
        uint4 vd;
        vd.x = f2tf(vsrc.x); vd.y = f2tf(vsrc.y);
        vd.z = f2tf(vsrc.z); vd.w = f2tf(vsrc.w);
        ((uint4*)dst)[idx] = vd;
    }
}

// ---------------- cp.async TF32 GEMM: BM=128 BN=128 BK=32, 3 stages ----------------
#define ASTRIDE 36                                // 32 + 4 pad
#define STAGE_WORDS (128 * ASTRIDE + 32 * 136)    // 8960
#define GEMM_SMEM (3 * STAGE_WORDS * 4)           // 107520 B

__device__ __forceinline__ void issue_tile(uint32_t sbase,
                                           const uint32_t* __restrict__ A,
                                           const uint32_t* __restrict__ B,
                                           int K, int k0, int row0, int col0, int tid)
{
    // A: 128 rows x 32 k-words; 2 threads/row, 16 words each (4 x cp16)
    int arow = tid >> 1, ak = (tid & 1) * 16;
    const uint32_t* asrc = A + (size_t)(row0 + arow) * K + k0 + ak;
    uint32_t adst = sbase + (arow * ASTRIDE + ak) * 4;
#pragma unroll
    for (int i = 0; i < 4; i++) cp16(adst + i * 16, asrc + i * 4);
    // B: 32 rows x 128 n-words; 8 threads/row, 16 words each (4 x cp16)
    int brow = tid >> 3, bc = (tid & 7) * 16;
    const uint32_t* bsrc = B + (size_t)(k0 + brow) * 768 + col0 + bc;
    uint32_t bdst = sbase + (128 * ASTRIDE + brow * 136 + bc) * 4;
#pragma unroll
    for (int i = 0; i < 4; i++) cp16(bdst + i * 16, bsrc + i * 4);
}

__device__ __forceinline__ void gemm_ca_body(const uint32_t* __restrict__ A,
                                             const uint32_t* __restrict__ B,
                                             const float* __restrict__ bias,
                                             const float* __restrict__ emul,
                                             float* __restrict__ C,
                                             int K, int act, int bx, int by)
{
    extern __shared__ uint32_t gsm[];
    uint32_t sbase = (uint32_t)__cvta_generic_to_shared(gsm);

    int tid = threadIdx.x;
    int wid = tid >> 5, lane = tid & 31;
    int warp_m = wid >> 2, warp_n = wid & 3;
    int group = lane >> 2, tg = lane & 3;
    int row0 = by * 128;
    int col0 = bx * 128;

    float acc[4][4][4];
#pragma unroll
    for (int mt = 0; mt < 4; mt++)
#pragma unroll
        for (int nt = 0; nt < 4; nt++)
#pragma unroll
            for (int r = 0; r < 4; r++) acc[mt][nt][r] = 0.f;

    int kt = K >> 5;
    issue_tile(sbase, A, B, K, 0, row0, col0, tid);
    CP_COMMIT();
    issue_tile(sbase + STAGE_WORDS * 4, A, B, K, 32, row0, col0, tid);
    CP_COMMIT();

    int stage = 0;
    for (int it = 0; it < kt; it++) {
        CP_WAIT1();
        __syncthreads();
        const uint32_t* As = gsm + stage * STAGE_WORDS;
        const uint32_t* Bs = As + 128 * ASTRIDE;

#pragma unroll
        for (int kc = 0; kc < 4; kc++) {
            int kb = kc * 8;
            uint32_t afr[4][4];
#pragma unroll
            for (int mt = 0; mt < 4; mt++) {
                int m = (warp_m * 64 + mt * 16 + group) * ASTRIDE;
                afr[mt][0] = As[m + kb + tg];
                afr[mt][1] = As[m + 8 * ASTRIDE + kb + tg];
                afr[mt][2] = As[m + kb + tg + 4];
                afr[mt][3] = As[m + 8 * ASTRIDE + kb + tg + 4];
            }
            uint32_t bfr[4][2];
#pragma unroll
            for (int nt = 0; nt < 4; nt++) {
                int n = warp_n * 32 + nt * 8 + group;
                bfr[nt][0] = Bs[(kb + tg) * 136 + n];
                bfr[nt][1] = Bs[(kb + tg + 4) * 136 + n];
            }
#pragma unroll
            for (int mt = 0; mt < 4; mt++)
#pragma unroll
                for (int nt = 0; nt < 4; nt++)
                    mma8(acc[mt][nt], afr[mt], bfr[nt]);
        }

        if (it + 2 < kt) {
            int nst = stage + 2; if (nst >= 3) nst -= 3;
            issue_tile(sbase + nst * STAGE_WORDS * 4, A, B, K,
                       (it + 2) * 32, row0, col0, tid);
        }
        CP_COMMIT();
        stage = stage + 1; if (stage == 3) stage = 0;
    }

    // epilogue
#pragma unroll
    for (int mt = 0; mt < 4; mt++) {
#pragma unroll
        for (int nt = 0; nt < 4; nt++) {
            int col = col0 + warp_n * 32 + nt * 8 + tg * 2;
            float b0 = bias ? bias[col]     : 0.f;
            float b1 = bias ? bias[col + 1] : 0.f;
#pragma unroll
            for (int half = 0; half < 2; half++) {
                int row = row0 + warp_m * 64 + mt * 16 + group + half * 8;
                float v0 = acc[mt][nt][half * 2 + 0] + b0;
                float v1 = acc[mt][nt][half * 2 + 1] + b1;
                if (act == 1) {
                    v0 = 1.f / (1.f + expf(-v0));
                    v1 = 1.f / (1.f + expf(-v1));
                }
                if (emul) {
                    v0 *= emul[(size_t)row * 768 + col];
                    v1 *= emul[(size_t)row * 768 + col + 1];
                }
                float2 r = make_float2(v0, v1);
                *(float2*)&C[(size_t)row * 768 + col] = r;
            }
        }
    }
}

__global__ __launch_bounds__(256) void tgemm_ca(const uint32_t* __restrict__ A,
                                                const uint32_t* __restrict__ B,
                                                const float* __restrict__ bias,
                                                const float* __restrict__ emul,
                                                float* __restrict__ C,
                                                int K, int act)
{
    gemm_ca_body(A, B, bias, emul, C, K, act, blockIdx.x, blockIdx.y);
}

__global__ __launch_bounds__(256) void tgemm_qkvg_ca(const uint32_t* __restrict__ alnt,
                                                     const uint32_t* __restrict__ wt,
                                                     const float* __restrict__ bq,
                                                     const float* __restrict__ bg,
                                                     float* __restrict__ q,
                                                     float* __restrict__ k,
                                                     float* __restrict__ v,
                                                     float* __restrict__ g)
{
    int zi = blockIdx.z;
    const uint32_t* B = wt + (size_t)zi * W768;
    const float* bias = (zi == 0) ? bq : (zi == 3) ? bg : nullptr;
    float* C          = (zi == 0) ? q  : (zi == 1) ? k  : (zi == 2) ? v  : g;
    int act           = (zi == 3) ? 1 : 0;
    gemm_ca_body(alnt, B, bias, nullptr, C, 768, act, blockIdx.x, blockIdx.y);
}

// ---------------- dual-B adaln GEMM (BN=64, writes tf32 aln) ----------------
#define AS_STRIDE 136
#define BS_STRIDE 72
__global__ __launch_bounds__(256) void adaln_kernel(const float* __restrict__ sln,
                                                    const float* __restrict__ ws,
                                                    const float* __restrict__ wskip,
                                                    const float* __restrict__ bs,
                                                    const float* __restrict__ alnr,
                                                    uint32_t* __restrict__ alnt)
{
    __shared__ uint32_t As [16 * AS_STRIDE];
    __shared__ uint32_t Bs1[16 * BS_STRIDE];
    __shared__ uint32_t Bs2[16 * BS_STRIDE];

    const int K = 384;
    int tid = threadIdx.x;
    int wid = tid >> 5, lane = tid & 31;
    int warp_m = wid >> 1, warp_n = wid & 1;
    int group = lane >> 2, tg = lane & 3;
    int row0 = blockIdx.y * 128;
    int col0 = blockIdx.x * 64;

    int arow = tid >> 1, akp = (tid & 1) * 8;
    int brow = tid >> 4, bcol = (tid & 15) * 4;

    const float* Abase = sln + (size_t)(row0 + arow) * K;

    float acc1[2][4][4], acc2[2][4][4];
#pragma unroll
    for (int mt = 0; mt < 2; mt++)
#pragma unroll
        for (int nt = 0; nt < 4; nt++)
#pragma unroll
            for (int r = 0; r < 4; r++) { acc1[mt][nt][r] = 0.f; acc2[mt][nt][r] = 0.f; }

    {
        float4 va0 = *(const float4*)(Abase + akp);
        float4 va1 = *(const float4*)(Abase + akp + 4);
        float4 vb1 = *(const float4*)(ws    + (size_t)brow * 768 + col0 + bcol);
        float4 vb2 = *(const float4*)(wskip + (size_t)brow * 768 + col0 + bcol);
        float av[8] = {va0.x, va0.y, va0.z, va0.w, va1.x, va1.y, va1.z, va1.w};
#pragma unroll
        for (int i = 0; i < 8; i++) As[(akp + i) * AS_STRIDE + arow] = f2tf(av[i]);
        float b1v[4] = {vb1.x, vb1.y, vb1.z, vb1.w};
        float b2v[4] = {vb2.x, vb2.y, vb2.z, vb2.w};
#pragma unroll
        for (int i = 0; i < 4; i++) {
            Bs1[brow * BS_STRIDE + bcol + i] = f2tf(b1v[i]);
            Bs2[brow * BS_STRIDE + bcol + i] = f2tf(b2v[i]);
        }
    }

    for (int k0 = 0; k0 < K; k0 += 16) {
        __syncthreads();
        bool has_next = (k0 + 16) < K;
        float4 va0, va1, vb1, vb2;
        if (has_next) {
            va0 = *(const float4*)(Abase + k0 + 16 + akp);
            va1 = *(const float4*)(Abase + k0 + 16 + akp + 4);
            vb1 = *(const float4*)(ws    + (size_t)(k0 + 16 + brow) * 768 + col0 + bcol);
            vb2 = *(const float4*)(wskip + (size_t)(k0 + 16 + brow) * 768 + col0 + bcol);
        }

#pragma unroll
        for (int kc = 0; kc < 2; kc++) {
            int kb = kc * 8;
            uint32_t afr[2][4];
#pragma unroll
            for (int mt = 0; mt < 2; mt++) {
                int m = warp_m * 32 + mt * 16 + group;
                afr[mt][0] = As[(kb + tg) * AS_STRIDE + m];
                afr[mt][1] = As[(kb + tg) * AS_STRIDE + m + 8];
                afr[mt][2] = As[(kb + tg + 4) * AS_STRIDE + m];
                afr[mt][3] = As[(kb + tg + 4) * AS_STRIDE + m + 8];
            }
#pragma unroll
            for (int nt = 0; nt < 4; nt++) {
                int n = warp_n * 32 + nt * 8 + group;
                uint32_t b1[2], b2[2];
                b1[0] = Bs1[(kb + tg) * BS_STRIDE + n];
                b1[1] = Bs1[(kb + tg + 4) * BS_STRIDE + n];
                b2[0] = Bs2[(kb + tg) * BS_STRIDE + n];
                b2[1] = Bs2[(kb + tg + 4) * BS_STRIDE + n];
#pragma unroll
                for (int mt = 0; mt < 2; mt++) {
                    mma8(acc1[mt][nt], afr[mt], b1);
                    mma8(acc2[mt][nt], afr[mt], b2);
                }
            }
        }

        __syncthreads();
        if (has_next) {
            float av[8] = {va0.x, va0.y, va0.z, va0.w, va1.x, va1.y, va1.z, va1.w};
#pragma unroll
            for (int i = 0; i < 8; i++) As[(akp + i) * AS_STRIDE + arow] = f2tf(av[i]);
            float b1v[4] = {vb1.x, vb1.y, vb1.z, vb1.w};
            float b2v[4] = {vb2.x, vb2.y, vb2.z, vb2.w};
#pragma unroll
            for (int i = 0; i < 4; i++) {
                Bs1[brow * BS_STRIDE + bcol + i] = f2tf(b1v[i]);
                Bs2[brow * BS_STRIDE + bcol + i] = f2tf(b2v[i]);
            }
        }
    }

#pragma unroll
    for (int mt = 0; mt < 2; mt++) {
#pragma unroll
        for (int nt = 0; nt < 4; nt++) {
            int col = col0 + warp_n * 32 + nt * 8 + tg * 2;
            float b0 = bs[col], b1 = bs[col + 1];
#pragma unroll
            for (int half = 0; half < 2; half++) {
                int row = row0 + warp_m * 32 + mt * 16 + group + half * 8;
                float s0 = 1.f / (1.f + expf(-(acc1[mt][nt][half * 2 + 0] + b0)));
                float s1 = 1.f / (1.f + expf(-(acc1[mt][nt][half * 2 + 1] + b1)));
                float r0 = s0 * alnr[(size_t)row * 768 + col]     + acc2[mt][nt][half * 2 + 0];
                float r1 = s1 * alnr[(size_t)row * 768 + col + 1] + acc2[mt][nt][half * 2 + 1];
                uint2 rr;
                rr.x = f2tf(r0);
                rr.y = f2tf(r1);
                *(uint2*)&alnt[(size_t)row * 768 + col] = rr;
            }
        }
    }
}

// ---------------- bias = LN(z)*gamma @ wz (fused LN + TF32 GEMM) ----------------
#define ZAS 132
#define ZBS 24
#define BIAS2_SMEM ((128 * ZAS + 128 * ZBS) * 4)
__global__ __launch_bounds__(256, 2) void bias2_kernel(const float* __restrict__ z,
                                                       const float* __restrict__ gamma,
                                                       const float* __restrict__ wz,
                                                       float* __restrict__ out)
{
    extern __shared__ uint32_t dyn[];
    uint32_t* As = dyn;
    uint32_t* Bs = dyn + 128 * ZAS;
    float*    st = (float*)dyn;

    int tid = threadIdx.x;
    int wid = tid >> 5, lane = tid & 31;
    int blk = blockIdx.x;

    for (int idx = tid; idx < 2048; idx += 256) {
        int c = idx >> 4, h = idx & 15;
        Bs[c * ZBS + h] = f2tf(wz[idx]);
    }

    float4 g4 = *(const float4*)(gamma + lane * 4);

    const float* zbase = z + ((size_t)blk * 128 + wid) * CZ + lane * 4;
    float4 rv[16];
#pragma unroll
    for (int i = 0; i < 16; i++)
        rv[i] = *(const float4*)(zbase + (size_t)i * 8 * CZ);

#pragma unroll
    for (int i = 0; i < 16; i++) {
        int r = wid + 8 * i;
        float4 x = rv[i];
        float sum = x.x + x.y + x.z + x.w;
#pragma unroll
        for (int o = 16; o; o >>= 1) sum += __shfl_xor_sync(0xffffffffu, sum, o);
        float m = sum * (1.0f / CZ);
        float d0 = x.x - m, d1 = x.y - m, d2 = x.z - m, d3 = x.w - m;
        float ss = d0 * d0 + d1 * d1 + d2 * d2 + d3 * d3;
#pragma unroll
        for (int o = 16; o; o >>= 1) ss += __shfl_xor_sync(0xffffffffu, ss, o);
        float inv = rsqrtf(ss * (1.0f / CZ) + 1e-5f);
        uint4 pk;
        pk.x = f2tf(d0 * inv * g4.x);
        pk.y = f2tf(d1 * inv * g4.y);
        pk.z = f2tf(d2 * inv * g4.z);
        pk.w = f2tf(d3 * inv * g4.w);
        *(uint4*)&As[r * ZAS + lane * 4] = pk;
    }
    __syncthreads();

    int group = lane >> 2, tg = lane & 3;
    int m0 = wid * 16;
    float acc[2][4];
#pragma unroll
    for (int nt = 0; nt < 2; nt++)
#pragma unroll
        for (int r = 0; r < 4; r++) acc[nt][r] = 0.f;

#pragma unroll
    for (int ks = 0; ks < 16; ks++) {
        int kb = ks * 8;
        uint32_t a[4];
        a[0] = As[(m0 + group)     * ZAS + kb + tg];
        a[1] = As[(m0 + group + 8) * ZAS + kb + tg];
        a[2] = As[(m0 + group)     * ZAS + kb + tg + 4];
        a[3] = As[(m0 + group + 8) * ZAS + kb + tg + 4];
        uint32_t b0[2], b1[2];
        b0[0] = Bs[(kb + tg)     * ZBS + group];
        b0[1] = Bs[(kb + tg + 4) * ZBS + group];
        b1[0] = Bs[(kb + tg)     * ZBS + 8 + group];
        b1[1] = Bs[(kb + tg + 4) * ZBS + 8 + group];
        mma8(acc[0], a, b0);
        mma8(acc[1], a, b1);
    }
    __syncthreads();

#pragma unroll
    for (int nt = 0; nt < 2; nt++)
#pragma unroll
        for (int half = 0; half < 2; half++) {
            int m  = m0 + group + half * 8;
            int h0 = nt * 8 + tg * 2;
            st[h0       * 129 + m] = acc[nt][half * 2 + 0];
            st[(h0 + 1) * 129 + m] = acc[nt][half * 2 + 1];
        }
    __syncthreads();

    int wwin = blk >> 5;
    int rembase = (blk & 31) * 128;
#pragma unroll
    for (int i = 0; i < 8; i++) {
        int idx = tid + 256 * i;
        int h = idx >> 7, m = idx & 127;
        out[((size_t)(wwin * 16 + h)) * 4096 + rembase + m] = st[h * 129 + m];
    }
}

// ---------------- local attention (lean) -> writes tf32(g * o) ----------------
#define ATTN_SMEM ((32 * 48 + 2 * 128 * 52) * 4)
__global__ __launch_bounds__(256) void attn_kernel(const float* __restrict__ q,
                                                   const float* __restrict__ k,
                                                   const float* __restrict__ v,
                                                   const float* __restrict__ bias,
                                                   const float* __restrict__ gate,
                                                   uint32_t* __restrict__ t1)
{
    extern __shared__ float sm[];
    float* qs = sm;
    float* ks = sm + 32 * 48;
    float* vs = ks + 128 * 52;
    int w = blockIdx.x, h = blockIdx.y;
    int tid = threadIdx.x;

    {
        const float* qbase = q + (size_t)w * 32 * CA + h * 48;
#pragma unroll
        for (int it = 0; it < 2; it++) {
            int i = tid + it * 256;
            if (i < 384) {
                int r = i / 12, c = i - r * 12;
                *(float4*)&qs[r * 48 + c * 4] =
                    *(const float4*)(qbase + (size_t)r * CA + c * 4);
            }
        }
    }
    {
        int r = tid >> 1, half = tid & 1;
        int tok = w * 32 - 48 + r;
        tok = tok < 0 ? 0 : (tok > 4095 ? 4095 : tok);
        const float4* kg = (const float4*)(k + (size_t)tok * CA + h * 48) + half * 6;
        const float4* vg = (const float4*)(v + (size_t)tok * CA + h * 48) + half * 6;
        float* kd = &ks[r * 52 + half * 24];
        float* vd = &vs[r * 52 + half * 24];
#pragma unroll
        for (int j = 0; j < 6; j++) {
            *(float4*)&kd[j * 4] = kg[j];
            *(float4*)&vd[j * 4] = vg[j];
        }
    }
    __syncthreads();

    int qi = tid >> 3, g = tid & 7;
    float4 qreg[12];
#pragma unroll
    for (int j = 0; j < 12; j++) qreg[j] = *(const float4*)&qs[qi * 48 + 4 * j];

    const float scale = 0.14433756729740643f;
    float sc[16];
    const float* bp = bias + ((size_t)(w * 16 + h) * 32 + qi) * 128;
#pragma unroll
    for (int jj = 0; jj < 16; jj++) {
        int kj = g + 8 * jj;
        int tok = w * 32 - 48 + kj;
        if (tok < 0 || tok >= 4096) { sc[jj] = -1e9f; continue; }
        const float4* kp = (const float4*)&ks[kj * 52];
        float a0 = 0.f, a1 = 0.f, a2 = 0.f, a3 = 0.f;
#pragma unroll
        for (int j = 0; j < 12; j++) {
            float4 kv = kp[j];
            a0 += qreg[j].x * kv.x;
            a1 += qreg[j].y * kv.y;
            a2 += qreg[j].z * kv.z;
            a3 += qreg[j].w * kv.w;
        }
        sc[jj] = ((a0 + a1) + (a2 + a3)) * scale + bp[kj];
    }
    float mx = sc[0];
#pragma unroll
    for (int jj = 1; jj < 16; jj++) mx = fmaxf(mx, sc[jj]);
#pragma unroll
    for (int o2 = 1; o2 < 8; o2 <<= 1) mx = fmaxf(mx, __shfl_xor_sync(0xffffffffu, mx, o2));
    float sum = 0.f;
#pragma unroll
    for (int jj = 0; jj < 16; jj++) { sc[jj] = __expf(sc[jj] - mx); sum += sc[jj]; }
#pragma unroll
    for (int o2 = 1; o2 < 8; o2 <<= 1) sum += __shfl_xor_sync(0xffffffffu, sum, o2);
    float inv = 1.f / sum;

    float oa[48];
#pragma unroll
    for (int d = 0; d < 48; d++) oa[d] = 0.f;
#pragma unroll
    for (int jj = 0; jj < 16; jj++) {
        float p = sc[jj] * inv;
        const float4* vp = (const float4*)&vs[(g + 8 * jj) * 52];
#pragma unroll
        for (int j = 0; j < 12; j++) {
            float4 vv = vp[j];
            oa[4 * j + 0] += p * vv.x; oa[4 * j + 1] += p * vv.y;
            oa[4 * j + 2] += p * vv.z; oa[4 * j + 3] += p * vv.w;
        }
    }
#pragma unroll
    for (int o2 = 1; o2 < 8; o2 <<= 1)
#pragma unroll
        for (int d = 0; d < 48; d++)
            oa[d] += __shfl_xor_sync(0xffffffffu, oa[d], o2);

    size_t rowbase = (size_t)(w * 32 + qi) * CA + h * 48;
#pragma unroll
    for (int j = 0; j < 6; j++) {
        int d = g * 6 + j;
        float gv = gate[rowbase + d];
        t1[rowbase + d] = f2tf(gv * oa[d]);
    }
}

// ---------------- launch ----------------
extern "C" void kernel_launch(void* const* d_in, const int* in_sizes, int n_in,
                              void* d_out, int out_size)
{
    const float* a        = (const float*)d_in[0];
    const float* s        = (const float*)d_in[1];
    const float* z        = (const float*)d_in[2];
    const float* gamma_s  = (const float*)d_in[3];
    const float* ws       = (const float*)d_in[4];
    const float* bs       = (const float*)d_in[5];
    const float* wskip    = (const float*)d_in[6];
    const float* lnzg     = (const float*)d_in[7];
    const float* wz       = (const float*)d_in[8];
    const float* wq       = (const float*)d_in[9];
    const float* bq       = (const float*)d_in[10];
    const float* wk       = (const float*)d_in[11];
    const float* wv       = (const float*)d_in[12];
    const float* wg       = (const float*)d_in[13];
    const float* bg       = (const float*)d_in[14];
    const float* wo       = (const float*)d_in[15];
    const float* bo       = (const float*)d_in[16];
    const float* wlast    = (const float*)d_in[17];
    const float* blast    = (const float*)d_in[18];
    float* out = (float*)d_out;

    float *p_sln, *p_alnr, *p_t2, *p_q, *p_k, *p_v, *p_g, *p_bias;
    uint32_t *p_stf, *p_alnt, *p_t1t, *p_wt;
    cudaGetSymbolAddress((void**)&p_sln,  g_sln);
    cudaGetSymbolAddress((void**)&p_stf,  g_stf);
    cudaGetSymbolAddress((void**)&p_alnr, g_alnr);
    cudaGetSymbolAddress((void**)&p_alnt, g_alnt);
    cudaGetSymbolAddress((void**)&p_t2,   g_t2);
    cudaGetSymbolAddress((void**)&p_q,    g_q);
    cudaGetSymbolAddress((void**)&p_k,    g_k);
    cudaGetSymbolAddress((void**)&p_v,    g_v);
    cudaGetSymbolAddress((void**)&p_g,    g_g);
    cudaGetSymbolAddress((void**)&p_t1t,  g_t1t);
    cudaGetSymbolAddress((void**)&p_bias, g_bias);
    cudaGetSymbolAddress((void**)&p_wt,   g_wt);

    cudaFuncSetAttribute(attn_kernel,   cudaFuncAttributeMaxDynamicSharedMemorySize, ATTN_SMEM);
    cudaFuncSetAttribute(bias2_kernel,  cudaFuncAttributeMaxDynamicSharedMemorySize, BIAS2_SMEM);
    cudaFuncSetAttribute(tgemm_ca,      cudaFuncAttributeMaxDynamicSharedMemorySize, GEMM_SMEM);
    cudaFuncSetAttribute(tgemm_qkvg_ca, cudaFuncAttributeMaxDynamicSharedMemorySize, GEMM_SMEM);

    // 0: LN(s)+stf / LN(a) / weight tf32 conversion — all independent
    ln_fused_kernel<<<4192, 256>>>(s, gamma_s, p_sln, p_stf, a, p_alnr,
                                   wq, wk, wv, wg, wo, wlast, p_wt);

    // 1: aln = sigmoid(sln@ws + bs) * ln(a) + sln@wskip  (writes tf32 aln)
    adaln_kernel<<<dim3(12, 32), 256>>>(p_sln, ws, wskip, bs, p_alnr, p_alnt);

    // 2: pair-bias
    bias2_kernel<<<4096, 256, BIAS2_SMEM>>>(z, lnzg, wz, p_bias);

    // 3: Q/K/V/G projections (cp.async, BK=32)
    tgemm_qkvg_ca<<<dim3(6, 32, 4), 256, GEMM_SMEM>>>(p_alnt, p_wt, bq, bg,
                                                      p_q, p_k, p_v, p_g);

    // 4: attention -> t1 = tf32(g * o)
    attn_kernel<<<dim3(128, 16), 256, ATTN_SMEM>>>(p_q, p_k, p_v, p_bias, p_g, p_t1t);

    // 5: t2 = t1 @ wo + bo
    tgemm_ca<<<dim3(6, 32), 256, GEMM_SMEM>>>(p_t1t, p_wt + (size_t)4 * W768,
                                              bo, nullptr, p_t2, 768, 0);
    // 6: out = sigmoid(s @ wlast + blast) * t2
    tgemm_ca<<<dim3(6, 32), 256, GEMM_SMEM>>>(p_stf, p_wt + (size_t)5 * W768,
                                              blast, p_t2, out, 384, 1);
}

// round 13
// speedup vs baseline: 1.2328x; 1.1790x over previous
#include <cuda_runtime.h>
#include <math.h>
#include <stdint.h>

// Problem constants
#define N_TOK 4096
#define CA 768
#define CS 384
#define CZ 128
#define NH 16
#define HD 48

#define W768 589824     // 768*768
#define W384 294912     // 384*768

// ---------------- scratch ----------------
__device__ __align__(16) float    g_sln [N_TOK * CS];
__device__ __align__(16) uint32_t g_stf [N_TOK * CS];     // tf32(s)
__device__ __align__(16) float    g_alnr[N_TOK * CA];
__device__ __align__(16) uint32_t g_alnt[N_TOK * CA];     // tf32(aln)
__device__ __align__(16) float    g_t2  [N_TOK * CA];     // sigmoid(s@wlast+blast)
__device__ __align__(16) float    g_q   [N_TOK * CA];
__device__ __align__(16) float    g_k   [N_TOK * CA];
__device__ __align__(16) float    g_v   [N_TOK * CA];
__device__ __align__(16) float    g_g   [N_TOK * CA];
__device__ __align__(16) uint32_t g_t1t [N_TOK * CA];     // tf32(g*o)
__device__ __align__(16) float    g_bias[NH * 128 * 32 * 128];
__device__ __align__(16) uint32_t g_wt  [5 * W768 + W384]; // wq wk wv wg wo | wlast

// ---------------- TF32 helpers ----------------
__device__ __forceinline__ uint32_t f2tf(float x)
{
    uint32_t r;
    asm("cvt.rna.tf32.f32 %0, %1;" : "=r"(r) : "f"(x));
    return r;
}

__device__ __forceinline__ void mma8(float* c, const uint32_t* a, const uint32_t* b)
{
    asm volatile("mma.sync.aligned.m16n8k8.row.col.f32.tf32.tf32.f32 "
                 "{%0,%1,%2,%3}, {%4,%5,%6,%7}, {%8,%9}, {%0,%1,%2,%3};"
                 : "+f"(c[0]), "+f"(c[1]), "+f"(c[2]), "+f"(c[3])
                 : "r"(a[0]), "r"(a[1]), "r"(a[2]), "r"(a[3]),
                   "r"(b[0]), "r"(b[1]));
}

__device__ __forceinline__ void cp16(uint32_t dst, const void* src)
{
    asm volatile("cp.async.cg.shared.global [%0], [%1], 16;" :: "r"(dst), "l"(src));
}
#define CP_COMMIT() asm volatile("cp.async.commit_group;")
#define CP_WAIT1()  asm volatile("cp.async.wait_group 1;")

// ---------------- fused LN + weight-convert kernel ----------------
__global__ __launch_bounds__(256) void ln_fused_kernel(const float* __restrict__ s,
                                                       const float* __restrict__ gamma,
                                                       float* __restrict__ sln,
                                                       uint32_t* __restrict__ stf,
                                                       const float* __restrict__ a,
                                                       float* __restrict__ alnr,
                                                       const float* __restrict__ wq,
                                                       const float* __restrict__ wk,
                                                       const float* __restrict__ wv,
                                                       const float* __restrict__ wg,
                                                       const float* __restrict__ wo,
                                                       const float* __restrict__ wlast,
                                                       uint32_t* __restrict__ wt)
{
    int lane = threadIdx.x & 31;
    int bx = blockIdx.x;
    if (bx < 512) {
        int row = bx * 8 + (threadIdx.x >> 5);
        const float* x = s + (size_t)row * CS;
        float v[12];
        float sum = 0.f;
#pragma unroll
        for (int i = 0; i < 12; i++) { v[i] = x[lane + 32 * i]; sum += v[i]; }
#pragma unroll
        for (int o = 16; o; o >>= 1) sum += __shfl_xor_sync(0xffffffffu, sum, o);
        float m = sum * (1.0f / CS);
        float ss = 0.f;
#pragma unroll
        for (int i = 0; i < 12; i++) { float d = v[i] - m; ss += d * d; }
#pragma unroll
        for (int o = 16; o; o >>= 1) ss += __shfl_xor_sync(0xffffffffu, ss, o);
        float inv = rsqrtf(ss * (1.0f / CS) + 1e-5f);
        float* op = sln + (size_t)row * CS;
        uint32_t* op2 = stf + (size_t)row * CS;
#pragma unroll
        for (int i = 0; i < 12; i++) {
            op [lane + 32 * i] = (v[i] - m) * inv * gamma[lane + 32 * i];
            op2[lane + 32 * i] = f2tf(v[i]);
        }
    } else if (bx < 1024) {
        int row = (bx - 512) * 8 + (threadIdx.x >> 5);
        const float* x = a + (size_t)row * CA;
        float v[24];
        float sum = 0.f;
#pragma unroll
        for (int i = 0; i < 24; i++) { v[i] = x[lane + 32 * i]; sum += v[i]; }
#pragma unroll
        for (int o = 16; o; o >>= 1) sum += __shfl_xor_sync(0xffffffffu, sum, o);
        float m = sum * (1.0f / CA);
        float ss = 0.f;
#pragma unroll
        for (int i = 0; i < 24; i++) { float d = v[i] - m; ss += d * d; }
#pragma unroll
        for (int o = 16; o; o >>= 1) ss += __shfl_xor_sync(0xffffffffu, ss, o);
        float inv = rsqrtf(ss * (1.0f / CA) + 1e-5f);
        float* op = alnr + (size_t)row * CA;
#pragma unroll
        for (int i = 0; i < 24; i++)
            op[lane + 32 * i] = (v[i] - m) * inv;
    } else {
        int b = bx - 1024;
        const float* src;
        uint32_t* dst;
        int local;
        if (b < 2880) {
            int seg = b / 576;
            local = b - seg * 576;
            src = (seg == 0) ? wq : (seg == 1) ? wk : (seg == 2) ? wv
                : (seg == 3) ? wg : wo;
            dst = wt + (size_t)seg * W768;
        } else {
            local = b - 2880;
            src = wlast;
            dst = wt + (size_t)5 * W768;
        }
        int idx = local * 256 + threadIdx.x;
        float4 vsrc = ((const float4*)src)[idx];
        uint4 vd;
        vd.x = f2tf(vsrc.x); vd.y = f2tf(vsrc.y);
        vd.z = f2tf(vsrc.z); vd.w = f2tf(vsrc.w);
        ((uint4*)dst)[idx] = vd;
    }
}

// ---------------- cp.async TF32 GEMM: BM=128 BN=128 BK=16, 3 stages (R10) ------------
#define ASTRIDE 20
#define STAGE_WORDS (128 * ASTRIDE + 16 * 136)   // 4736
#define GEMM_SMEM (3 * STAGE_WORDS * 4)          // 56832 B

__device__ __forceinline__ void issue_tile(uint32_t sbase,
                                           const uint32_t* __restrict__ A,
                                           const uint32_t* __restrict__ B,
                                           int K, int k0, int row0, int col0, int tid)
{
    int arow = tid >> 1, ac = (tid & 1) * 2;
    const uint32_t* asrc = A + (size_t)(row0 + arow) * K + k0 + ac * 4;
    uint32_t adst = sbase + (arow * ASTRIDE + ac * 4) * 4;
    cp16(adst, asrc);
    cp16(adst + 16, asrc + 4);
    int brow = tid >> 4, bc = (tid & 15) * 2;
    const uint32_t* bsrc = B + (size_t)(k0 + brow) * 768 + col0 + bc * 4;
    uint32_t bdst = sbase + (128 * ASTRIDE + brow * 136 + bc * 4) * 4;
    cp16(bdst, bsrc);
    cp16(bdst + 16, bsrc + 4);
}

__device__ __forceinline__ void gemm_ca_body(const uint32_t* __restrict__ A,
                                             const uint32_t* __restrict__ B,
                                             const float* __restrict__ bias,
                                             const float* __restrict__ emul,
                                             float* __restrict__ C,
                                             int K, int act, int bx, int by)
{
    extern __shared__ uint32_t gsm[];
    uint32_t sbase = (uint32_t)__cvta_generic_to_shared(gsm);

    int tid = threadIdx.x;
    int wid = tid >> 5, lane = tid & 31;
    int warp_m = wid >> 2, warp_n = wid & 3;
    int group = lane >> 2, tg = lane & 3;
    int row0 = by * 128;
    int col0 = bx * 128;

    float acc[4][4][4];
#pragma unroll
    for (int mt = 0; mt < 4; mt++)
#pragma unroll
        for (int nt = 0; nt < 4; nt++)
#pragma unroll
            for (int r = 0; r < 4; r++) acc[mt][nt][r] = 0.f;

    int kt = K >> 4;
    issue_tile(sbase, A, B, K, 0, row0, col0, tid);
    CP_COMMIT();
    issue_tile(sbase + STAGE_WORDS * 4, A, B, K, 16, row0, col0, tid);
    CP_COMMIT();

    int stage = 0;
    for (int it = 0; it < kt; it++) {
        CP_WAIT1();
        __syncthreads();
        const uint32_t* As = gsm + stage * STAGE_WORDS;
        const uint32_t* Bs = As + 128 * ASTRIDE;

#pragma unroll
        for (int kc = 0; kc < 2; kc++) {
            int kb = kc * 8;
            uint32_t afr[4][4];
#pragma unroll
            for (int mt = 0; mt < 4; mt++) {
                int m = (warp_m * 64 + mt * 16 + group) * ASTRIDE;
                afr[mt][0] = As[m + kb + tg];
                afr[mt][1] = As[m + 8 * ASTRIDE + kb + tg];
                afr[mt][2] = As[m + kb + tg + 4];
                afr[mt][3] = As[m + 8 * ASTRIDE + kb + tg + 4];
            }
            uint32_t bfr[4][2];
#pragma unroll
            for (int nt = 0; nt < 4; nt++) {
                int n = warp_n * 32 + nt * 8 + group;
                bfr[nt][0] = Bs[(kb + tg) * 136 + n];
                bfr[nt][1] = Bs[(kb + tg + 4) * 136 + n];
            }
#pragma unroll
            for (int mt = 0; mt < 4; mt++)
#pragma unroll
                for (int nt = 0; nt < 4; nt++)
                    mma8(acc[mt][nt], afr[mt], bfr[nt]);
        }

        if (it + 2 < kt) {
            int nst = stage + 2; if (nst >= 3) nst -= 3;
            issue_tile(sbase + nst * STAGE_WORDS * 4, A, B, K,
                       (it + 2) * 16, row0, col0, tid);
        }
        CP_COMMIT();
        stage = stage + 1; if (stage == 3) stage = 0;
    }

#pragma unroll
    for (int mt = 0; mt < 4; mt++) {
#pragma unroll
        for (int nt = 0; nt < 4; nt++) {
            int col = col0 + warp_n * 32 + nt * 8 + tg * 2;
            float b0 = bias ? bias[col]     : 0.f;
            float b1 = bias ? bias[col + 1] : 0.f;
#pragma unroll
            for (int half = 0; half < 2; half++) {
                int row = row0 + warp_m * 64 + mt * 16 + group + half * 8;
                float v0 = acc[mt][nt][half * 2 + 0] + b0;
                float v1 = acc[mt][nt][half * 2 + 1] + b1;
                if (act == 1) {
                    v0 = 1.f / (1.f + expf(-v0));
                    v1 = 1.f / (1.f + expf(-v1));
                }
                if (emul) {
                    v0 *= emul[(size_t)row * 768 + col];
                    v1 *= emul[(size_t)row * 768 + col + 1];
                }
                float2 r = make_float2(v0, v1);
                *(float2*)&C[(size_t)row * 768 + col] = r;
            }
        }
    }
}

__global__ __launch_bounds__(256) void tgemm_ca(const uint32_t* __restrict__ A,
                                                const uint32_t* __restrict__ B,
                                                const float* __restrict__ bias,
                                                const float* __restrict__ emul,
                                                float* __restrict__ C,
                                                int K, int act)
{
    gemm_ca_body(A, B, bias, emul, C, K, act, blockIdx.x, blockIdx.y);
}

// Q/K/V/G projections + wlast-sigmoid GEMM in ONE homogeneous launch (gridDim.z = 5)
__global__ __launch_bounds__(256) void tgemm_qkvg5_ca(const uint32_t* __restrict__ alnt,
                                                      const uint32_t* __restrict__ stf,
                                                      const uint32_t* __restrict__ wt,
                                                      const float* __restrict__ bq,
                                                      const float* __restrict__ bg,
                                                      const float* __restrict__ blast,
                                                      float* __restrict__ q,
                                                      float* __restrict__ k,
                                                      float* __restrict__ v,
                                                      float* __restrict__ g,
                                                      float* __restrict__ t2)
{
    int zi = blockIdx.z;
    if (zi < 4) {
        const uint32_t* B = wt + (size_t)zi * W768;
        const float* bias = (zi == 0) ? bq : (zi == 3) ? bg : nullptr;
        float* C          = (zi == 0) ? q  : (zi == 1) ? k  : (zi == 2) ? v  : g;
        int act           = (zi == 3) ? 1 : 0;
        gemm_ca_body(alnt, B, bias, nullptr, C, 768, act, blockIdx.x, blockIdx.y);
    } else {
        // t2 = sigmoid(s @ wlast + blast)  — depends only on inputs
        gemm_ca_body(stf, wt + (size_t)5 * W768, blast, nullptr, t2, 384, 1,
                     blockIdx.x, blockIdx.y);
    }
}

// ---------------- dual-B adaln GEMM (BN=64, writes tf32 aln) ----------------
#define AS_STRIDE 136
#define BS_STRIDE 72
__global__ __launch_bounds__(256) void adaln_kernel(const float* __restrict__ sln,
                                                    const float* __restrict__ ws,
                                                    const float* __restrict__ wskip,
                                                    const float* __restrict__ bs,
                                                    const float* __restrict__ alnr,
                                                    uint32_t* __restrict__ alnt)
{
    __shared__ uint32_t As [16 * AS_STRIDE];
    __shared__ uint32_t Bs1[16 * BS_STRIDE];
    __shared__ uint32_t Bs2[16 * BS_STRIDE];

    const int K = 384;
    int tid = threadIdx.x;
    int wid = tid >> 5, lane = tid & 31;
    int warp_m = wid >> 1, warp_n = wid & 1;
    int group = lane >> 2, tg = lane & 3;
    int row0 = blockIdx.y * 128;
    int col0 = blockIdx.x * 64;

    int arow = tid >> 1, akp = (tid & 1) * 8;
    int brow = tid >> 4, bcol = (tid & 15) * 4;

    const float* Abase = sln + (size_t)(row0 + arow) * K;

    float acc1[2][4][4], acc2[2][4][4];
#pragma unroll
    for (int mt = 0; mt < 2; mt++)
#pragma unroll
        for (int nt = 0; nt < 4; nt++)
#pragma unroll
            for (int r = 0; r < 4; r++) { acc1[mt][nt][r] = 0.f; acc2[mt][nt][r] = 0.f; }

    {
        float4 va0 = *(const float4*)(Abase + akp);
        float4 va1 = *(const float4*)(Abase + akp + 4);
        float4 vb1 = *(const float4*)(ws    + (size_t)brow * 768 + col0 + bcol);
        float4 vb2 = *(const float4*)(wskip + (size_t)brow * 768 + col0 + bcol);
        float av[8] = {va0.x, va0.y, va0.z, va0.w, va1.x, va1.y, va1.z, va1.w};
#pragma unroll
        for (int i = 0; i < 8; i++) As[(akp + i) * AS_STRIDE + arow] = f2tf(av[i]);
        float b1v[4] = {vb1.x, vb1.y, vb1.z, vb1.w};
        float b2v[4] = {vb2.x, vb2.y, vb2.z, vb2.w};
#pragma unroll
        for (int i = 0; i < 4; i++) {
            Bs1[brow * BS_STRIDE + bcol + i] = f2tf(b1v[i]);
            Bs2[brow * BS_STRIDE + bcol + i] = f2tf(b2v[i]);
        }
    }

    for (int k0 = 0; k0 < K; k0 += 16) {
        __syncthreads();
        bool has_next = (k0 + 16) < K;
        float4 va0, va1, vb1, vb2;
        if (has_next) {
            va0 = *(const float4*)(Abase + k0 + 16 + akp);
            va1 = *(const float4*)(Abase + k0 + 16 + akp + 4);
            vb1 = *(const float4*)(ws    + (size_t)(k0 + 16 + brow) * 768 + col0 + bcol);
            vb2 = *(const float4*)(wskip + (size_t)(k0 + 16 + brow) * 768 + col0 + bcol);
        }

#pragma unroll
        for (int kc = 0; kc < 2; kc++) {
            int kb = kc * 8;
            uint32_t afr[2][4];
#pragma unroll
            for (int mt = 0; mt < 2; mt++) {
                int m = warp_m * 32 + mt * 16 + group;
                afr[mt][0] = As[(kb + tg) * AS_STRIDE + m];
                afr[mt][1] = As[(kb + tg) * AS_STRIDE + m + 8];
                afr[mt][2] = As[(kb + tg + 4) * AS_STRIDE + m];
                afr[mt][3] = As[(kb + tg + 4) * AS_STRIDE + m + 8];
            }
#pragma unroll
            for (int nt = 0; nt < 4; nt++) {
                int n = warp_n * 32 + nt * 8 + group;
                uint32_t b1[2], b2[2];
                b1[0] = Bs1[(kb + tg) * BS_STRIDE + n];
                b1[1] = Bs1[(kb + tg + 4) * BS_STRIDE + n];
                b2[0] = Bs2[(kb + tg) * BS_STRIDE + n];
                b2[1] = Bs2[(kb + tg + 4) * BS_STRIDE + n];
#pragma unroll
                for (int mt = 0; mt < 2; mt++) {
                    mma8(acc1[mt][nt], afr[mt], b1);
                    mma8(acc2[mt][nt], afr[mt], b2);
                }
            }
        }

        __syncthreads();
        if (has_next) {
            float av[8] = {va0.x, va0.y, va0.z, va0.w, va1.x, va1.y, va1.z, va1.w};
#pragma unroll
            for (int i = 0; i < 8; i++) As[(akp + i) * AS_STRIDE + arow] = f2tf(av[i]);
            float b1v[4] = {vb1.x, vb1.y, vb1.z, vb1.w};
            float b2v[4] = {vb2.x, vb2.y, vb2.z, vb2.w};
#pragma unroll
            for (int i = 0; i < 4; i++) {
                Bs1[brow * BS_STRIDE + bcol + i] = f2tf(b1v[i]);
                Bs2[brow * BS_STRIDE + bcol + i] = f2tf(b2v[i]);
            }
        }
    }

#pragma unroll
    for (int mt = 0; mt < 2; mt++) {
#pragma unroll
        for (int nt = 0; nt < 4; nt++) {
            int col = col0 + warp_n * 32 + nt * 8 + tg * 2;
            float b0 = bs[col], b1 = bs[col + 1];
#pragma unroll
            for (int half = 0; half < 2; half++) {
                int row = row0 + warp_m * 32 + mt * 16 + group + half * 8;
                float s0 = 1.f / (1.f + expf(-(acc1[mt][nt][half * 2 + 0] + b0)));
                float s1 = 1.f / (1.f + expf(-(acc1[mt][nt][half * 2 + 1] + b1)));
                float r0 = s0 * alnr[(size_t)row * 768 + col]     + acc2[mt][nt][half * 2 + 0];
                float r1 = s1 * alnr[(size_t)row * 768 + col + 1] + acc2[mt][nt][half * 2 + 1];
                uint2 rr;
                rr.x = f2tf(r0);
                rr.y = f2tf(r1);
                *(uint2*)&alnt[(size_t)row * 768 + col] = rr;
            }
        }
    }
}

// ---------------- bias = LN(z)*gamma @ wz (fused LN + TF32 GEMM) ----------------
#define ZAS 132
#define ZBS 24
#define BIAS2_SMEM ((128 * ZAS + 128 * ZBS) * 4)
__global__ __launch_bounds__(256, 2) void bias2_kernel(const float* __restrict__ z,
                                                       const float* __restrict__ gamma,
                                                       const float* __restrict__ wz,
                                                       float* __restrict__ out)
{
    extern __shared__ uint32_t dyn[];
    uint32_t* As = dyn;
    uint32_t* Bs = dyn + 128 * ZAS;
    float*    st = (float*)dyn;

    int tid = threadIdx.x;
    int wid = tid >> 5, lane = tid & 31;
    int blk = blockIdx.x;

    for (int idx = tid; idx < 2048; idx += 256) {
        int c = idx >> 4, h = idx & 15;
        Bs[c * ZBS + h] = f2tf(wz[idx]);
    }

    float4 g4 = *(const float4*)(gamma + lane * 4);

    const float* zbase = z + ((size_t)blk * 128 + wid) * CZ + lane * 4;
    float4 rv[16];
#pragma unroll
    for (int i = 0; i < 16; i++)
        rv[i] = *(const float4*)(zbase + (size_t)i * 8 * CZ);

#pragma unroll
    for (int i = 0; i < 16; i++) {
        int r = wid + 8 * i;
        float4 x = rv[i];
        float sum = x.x + x.y + x.z + x.w;
#pragma unroll
        for (int o = 16; o; o >>= 1) sum += __shfl_xor_sync(0xffffffffu, sum, o);
        float m = sum * (1.0f / CZ);
        float d0 = x.x - m, d1 = x.y - m, d2 = x.z - m, d3 = x.w - m;
        float ss = d0 * d0 + d1 * d1 + d2 * d2 + d3 * d3;
#pragma unroll
        for (int o = 16; o; o >>= 1) ss += __shfl_xor_sync(0xffffffffu, ss, o);
        float inv = rsqrtf(ss * (1.0f / CZ) + 1e-5f);
        uint4 pk;
        pk.x = f2tf(d0 * inv * g4.x);
        pk.y = f2tf(d1 * inv * g4.y);
        pk.z = f2tf(d2 * inv * g4.z);
        pk.w = f2tf(d3 * inv * g4.w);
        *(uint4*)&As[r * ZAS + lane * 4] = pk;
    }
    __syncthreads();

    int group = lane >> 2, tg = lane & 3;
    int m0 = wid * 16;
    float acc[2][4];
#pragma unroll
    for (int nt = 0; nt < 2; nt++)
#pragma unroll
        for (int r = 0; r < 4; r++) acc[nt][r] = 0.f;

#pragma unroll
    for (int ks = 0; ks < 16; ks++) {
        int kb = ks * 8;
        uint32_t a[4];
        a[0] = As[(m0 + group)     * ZAS + kb + tg];
        a[1] = As[(m0 + group + 8) * ZAS + kb + tg];
        a[2] = As[(m0 + group)     * ZAS + kb + tg + 4];
        a[3] = As[(m0 + group + 8) * ZAS + kb + tg + 4];
        uint32_t b0[2], b1[2];
        b0[0] = Bs[(kb + tg)     * ZBS + group];
        b0[1] = Bs[(kb + tg + 4) * ZBS + group];
        b1[0] = Bs[(kb + tg)     * ZBS + 8 + group];
        b1[1] = Bs[(kb + tg + 4) * ZBS + 8 + group];
        mma8(acc[0], a, b0);
        mma8(acc[1], a, b1);
    }
    __syncthreads();

#pragma unroll
    for (int nt = 0; nt < 2; nt++)
#pragma unroll
        for (int half = 0; half < 2; half++) {
            int m  = m0 + group + half * 8;
            int h0 = nt * 8 + tg * 2;
            st[h0       * 129 + m] = acc[nt][half * 2 + 0];
            st[(h0 + 1) * 129 + m] = acc[nt][half * 2 + 1];
        }
    __syncthreads();

    int wwin = blk >> 5;
    int rembase = (blk & 31) * 128;
#pragma unroll
    for (int i = 0; i < 8; i++) {
        int idx = tid + 256 * i;
        int h = idx >> 7, m = idx & 127;
        out[((size_t)(wwin * 16 + h)) * 4096 + rembase + m] = st[h * 129 + m];
    }
}

// ---------------- local attention (lean) -> writes tf32(g * o) ----------------
#define ATTN_SMEM ((32 * 48 + 2 * 128 * 52) * 4)
__global__ __launch_bounds__(256) void attn_kernel(const float* __restrict__ q,
                                                   const float* __restrict__ k,
                                                   const float* __restrict__ v,
                                                   const float* __restrict__ bias,
                                                   const float* __restrict__ gate,
                                                   uint32_t* __restrict__ t1)
{
    extern __shared__ float sm[];
    float* qs = sm;
    float* ks = sm + 32 * 48;
    float* vs = ks + 128 * 52;
    int w = blockIdx.x, h = blockIdx.y;
    int tid = threadIdx.x;

    {
        const float* qbase = q + (size_t)w * 32 * CA + h * 48;
#pragma unroll
        for (int it = 0; it < 2; it++) {
            int i = tid + it * 256;
            if (i < 384) {
                int r = i / 12, c = i - r * 12;
                *(float4*)&qs[r * 48 + c * 4] =
                    *(const float4*)(qbase + (size_t)r * CA + c * 4);
            }
        }
    }
    {
        int r = tid >> 1, half = tid & 1;
        int tok = w * 32 - 48 + r;
        tok = tok < 0 ? 0 : (tok > 4095 ? 4095 : tok);
        const float4* kg = (const float4*)(k + (size_t)tok * CA + h * 48) + half * 6;
        const float4* vg = (const float4*)(v + (size_t)tok * CA + h * 48) + half * 6;
        float* kd = &ks[r * 52 + half * 24];
        float* vd = &vs[r * 52 + half * 24];
#pragma unroll
        for (int j = 0; j < 6; j++) {
            *(float4*)&kd[j * 4] = kg[j];
            *(float4*)&vd[j * 4] = vg[j];
        }
    }
    __syncthreads();

    int qi = tid >> 3, g = tid & 7;
    float4 qreg[12];
#pragma unroll
    for (int j = 0; j < 12; j++) qreg[j] = *(const float4*)&qs[qi * 48 + 4 * j];

    const float scale = 0.14433756729740643f;
    float sc[16];
    const float* bp = bias + ((size_t)(w * 16 + h) * 32 + qi) * 128;
#pragma unroll
    for (int jj = 0; jj < 16; jj++) {
        int kj = g + 8 * jj;
        int tok = w * 32 - 48 + kj;
        if (tok < 0 || tok >= 4096) { sc[jj] = -1e9f; continue; }
        const float4* kp = (const float4*)&ks[kj * 52];
        float a0 = 0.f, a1 = 0.f, a2 = 0.f, a3 = 0.f;
#pragma unroll
        for (int j = 0; j < 12; j++) {
            float4 kv = kp[j];
            a0 += qreg[j].x * kv.x;
            a1 += qreg[j].y * kv.y;
            a2 += qreg[j].z * kv.z;
            a3 += qreg[j].w * kv.w;
        }
        sc[jj] = ((a0 + a1) + (a2 + a3)) * scale + bp[kj];
    }
    float mx = sc[0];
#pragma unroll
    for (int jj = 1; jj < 16; jj++) mx = fmaxf(mx, sc[jj]);
#pragma unroll
    for (int o2 = 1; o2 < 8; o2 <<= 1) mx = fmaxf(mx, __shfl_xor_sync(0xffffffffu, mx, o2));
    float sum = 0.f;
#pragma unroll
    for (int jj = 0; jj < 16; jj++) { sc[jj] = __expf(sc[jj] - mx); sum += sc[jj]; }
#pragma unroll
    for (int o2 = 1; o2 < 8; o2 <<= 1) sum += __shfl_xor_sync(0xffffffffu, sum, o2);
    float inv = 1.f / sum;

    float oa[48];
#pragma unroll
    for (int d = 0; d < 48; d++) oa[d] = 0.f;
#pragma unroll
    for (int jj = 0; jj < 16; jj++) {
        float p = sc[jj] * inv;
        const float4* vp = (const float4*)&vs[(g + 8 * jj) * 52];
#pragma unroll
        for (int j = 0; j < 12; j++) {
            float4 vv = vp[j];
            oa[4 * j + 0] += p * vv.x; oa[4 * j + 1] += p * vv.y;
            oa[4 * j + 2] += p * vv.z; oa[4 * j + 3] += p * vv.w;
        }
    }
#pragma unroll
    for (int o2 = 1; o2 < 8; o2 <<= 1)
#pragma unroll
        for (int d = 0; d < 48; d++)
            oa[d] += __shfl_xor_sync(0xffffffffu, oa[d], o2);

    size_t rowbase = (size_t)(w * 32 + qi) * CA + h * 48;
#pragma unroll
    for (int j = 0; j < 6; j++) {
        int d = g * 6 + j;
        float gv = gate[rowbase + d];
        t1[rowbase + d] = f2tf(gv * oa[d]);
    }
}

// ---------------- launch ----------------
extern "C" void kernel_launch(void* const* d_in, const int* in_sizes, int n_in,
                              void* d_out, int out_size)
{
    const float* a        = (const float*)d_in[0];
    const float* s        = (const float*)d_in[1];
    const float* z        = (const float*)d_in[2];
    const float* gamma_s  = (const float*)d_in[3];
    const float* ws       = (const float*)d_in[4];
    const float* bs       = (const float*)d_in[5];
    const float* wskip    = (const float*)d_in[6];
    const float* lnzg     = (const float*)d_in[7];
    const float* wz       = (const float*)d_in[8];
    const float* wq       = (const float*)d_in[9];
    const float* bq       = (const float*)d_in[10];
    const float* wk       = (const float*)d_in[11];
    const float* wv       = (const float*)d_in[12];
    const float* wg       = (const float*)d_in[13];
    const float* bg       = (const float*)d_in[14];
    const float* wo       = (const float*)d_in[15];
    const float* bo       = (const float*)d_in[16];
    const float* wlast    = (const float*)d_in[17];
    const float* blast    = (const float*)d_in[18];
    float* out = (float*)d_out;

    float *p_sln, *p_alnr, *p_t2, *p_q, *p_k, *p_v, *p_g, *p_bias;
    uint32_t *p_stf, *p_alnt, *p_t1t, *p_wt;
    cudaGetSymbolAddress((void**)&p_sln,  g_sln);
    cudaGetSymbolAddress((void**)&p_stf,  g_stf);
    cudaGetSymbolAddress((void**)&p_alnr, g_alnr);
    cudaGetSymbolAddress((void**)&p_alnt, g_alnt);
    cudaGetSymbolAddress((void**)&p_t2,   g_t2);
    cudaGetSymbolAddress((void**)&p_q,    g_q);
    cudaGetSymbolAddress((void**)&p_k,    g_k);
    cudaGetSymbolAddress((void**)&p_v,    g_v);
    cudaGetSymbolAddress((void**)&p_g,    g_g);
    cudaGetSymbolAddress((void**)&p_t1t,  g_t1t);
    cudaGetSymbolAddress((void**)&p_bias, g_bias);
    cudaGetSymbolAddress((void**)&p_wt,   g_wt);

    cudaFuncSetAttribute(attn_kernel,    cudaFuncAttributeMaxDynamicSharedMemorySize, ATTN_SMEM);
    cudaFuncSetAttribute(bias2_kernel,   cudaFuncAttributeMaxDynamicSharedMemorySize, BIAS2_SMEM);
    cudaFuncSetAttribute(tgemm_ca,       cudaFuncAttributeMaxDynamicSharedMemorySize, GEMM_SMEM);
    cudaFuncSetAttribute(tgemm_qkvg5_ca, cudaFuncAttributeMaxDynamicSharedMemorySize, GEMM_SMEM);

    // 0: LN(s)+stf / LN(a) / weight tf32 conversion — all independent
    ln_fused_kernel<<<4192, 256>>>(s, gamma_s, p_sln, p_stf, a, p_alnr,
                                   wq, wk, wv, wg, wo, wlast, p_wt);

    // 1: aln = sigmoid(sln@ws + bs) * ln(a) + sln@wskip  (writes tf32 aln)
    adaln_kernel<<<dim3(12, 32), 256>>>(p_sln, ws, wskip, bs, p_alnr, p_alnt);

    // 2: pair-bias
    bias2_kernel<<<4096, 256, BIAS2_SMEM>>>(z, lnzg, wz, p_bias);

    // 3: Q/K/V/G projections + wlast sigmoid GEMM (homogeneous 5-slice launch)
    tgemm_qkvg5_ca<<<dim3(6, 32, 5), 256, GEMM_SMEM>>>(p_alnt, p_stf, p_wt,
                                                       bq, bg, blast,
                                                       p_q, p_k, p_v, p_g, p_t2);

    // 4: attention -> t1 = tf32(g * o)
    attn_kernel<<<dim3(128, 16), 256, ATTN_SMEM>>>(p_q, p_k, p_v, p_bias, p_g, p_t1t);

    // 5: out = (t1 @ wo + bo) * t2
    tgemm_ca<<<dim3(6, 32), 256, GEMM_SMEM>>>(p_t1t, p_wt + (size_t)4 * W768,
                                              bo, p_t2, out, 768, 0);
}

// round 14
// speedup vs baseline: 1.2400x; 1.0059x over previous
#include <cuda_runtime.h>
#include <math.h>
#include <stdint.h>

// Problem constants
#define N_TOK 4096
#define CA 768
#define CS 384
#define CZ 128
#define NH 16
#define HD 48

#define W768 589824     // 768*768
#define W384 294912     // 384*768

// ---------------- scratch ----------------
__device__ __align__(16) float    g_sln [N_TOK * CS];
__device__ __align__(16) uint32_t g_stf [N_TOK * CS];     // tf32(s)
__device__ __align__(16) float    g_alnr[N_TOK * CA];
__device__ __align__(16) uint32_t g_alnt[N_TOK * CA];     // tf32(aln)
__device__ __align__(16) float    g_t2  [N_TOK * CA];     // sigmoid(s@wlast+blast)
__device__ __align__(16) float    g_q   [N_TOK * CA];
__device__ __align__(16) float    g_k   [N_TOK * CA];
__device__ __align__(16) float    g_v   [N_TOK * CA];
__device__ __align__(16) float    g_g   [N_TOK * CA];
__device__ __align__(16) uint32_t g_t1t [N_TOK * CA];     // tf32(g*o)
__device__ __align__(16) float    g_bias[NH * 128 * 32 * 128];
__device__ __align__(16) uint32_t g_wt  [5 * W768 + W384]; // wq wk wv wg wo | wlast

// ---------------- TF32 helpers ----------------
__device__ __forceinline__ uint32_t f2tf(float x)
{
    uint32_t r;
    asm("cvt.rna.tf32.f32 %0, %1;" : "=r"(r) : "f"(x));
    return r;
}

__device__ __forceinline__ void mma8(float* c, const uint32_t* a, const uint32_t* b)
{
    asm volatile("mma.sync.aligned.m16n8k8.row.col.f32.tf32.tf32.f32 "
                 "{%0,%1,%2,%3}, {%4,%5,%6,%7}, {%8,%9}, {%0,%1,%2,%3};"
                 : "+f"(c[0]), "+f"(c[1]), "+f"(c[2]), "+f"(c[3])
                 : "r"(a[0]), "r"(a[1]), "r"(a[2]), "r"(a[3]),
                   "r"(b[0]), "r"(b[1]));
}

__device__ __forceinline__ void cp16(uint32_t dst, const void* src)
{
    asm volatile("cp.async.cg.shared.global [%0], [%1], 16;" :: "r"(dst), "l"(src));
}
#define CP_COMMIT() asm volatile("cp.async.commit_group;")
#define CP_WAIT1()  asm volatile("cp.async.wait_group 1;")

// ---------------- fused LN + weight-convert kernel ----------------
__global__ __launch_bounds__(256) void ln_fused_kernel(const float* __restrict__ s,
                                                       const float* __restrict__ gamma,
                                                       float* __restrict__ sln,
                                                       uint32_t* __restrict__ stf,
                                                       const float* __restrict__ a,
                                                       float* __restrict__ alnr,
                                                       const float* __restrict__ wq,
                                                       const float* __restrict__ wk,
                                                       const float* __restrict__ wv,
                                                       const float* __restrict__ wg,
                                                       const float* __restrict__ wo,
                                                       const float* __restrict__ wlast,
                                                       uint32_t* __restrict__ wt)
{
    int lane = threadIdx.x & 31;
    int bx = blockIdx.x;
    if (bx < 512) {
        int row = bx * 8 + (threadIdx.x >> 5);
        const float* x = s + (size_t)row * CS;
        float v[12];
        float sum = 0.f;
#pragma unroll
        for (int i = 0; i < 12; i++) { v[i] = x[lane + 32 * i]; sum += v[i]; }
#pragma unroll
        for (int o = 16; o; o >>= 1) sum += __shfl_xor_sync(0xffffffffu, sum, o);
        float m = sum * (1.0f / CS);
        float ss = 0.f;
#pragma unroll
        for (int i = 0; i < 12; i++) { float d = v[i] - m; ss += d * d; }
#pragma unroll
        for (int o = 16; o; o >>= 1) ss += __shfl_xor_sync(0xffffffffu, ss, o);
        float inv = rsqrtf(ss * (1.0f / CS) + 1e-5f);
        float* op = sln + (size_t)row * CS;
        uint32_t* op2 = stf + (size_t)row * CS;
#pragma unroll
        for (int i = 0; i < 12; i++) {
            op [lane + 32 * i] = (v[i] - m) * inv * gamma[lane + 32 * i];
            op2[lane + 32 * i] = f2tf(v[i]);
        }
    } else if (bx < 1024) {
        int row = (bx - 512) * 8 + (threadIdx.x >> 5);
        const float* x = a + (size_t)row * CA;
        float v[24];
        float sum = 0.f;
#pragma unroll
        for (int i = 0; i < 24; i++) { v[i] = x[lane + 32 * i]; sum += v[i]; }
#pragma unroll
        for (int o = 16; o; o >>= 1) sum += __shfl_xor_sync(0xffffffffu, sum, o);
        float m = sum * (1.0f / CA);
        float ss = 0.f;
#pragma unroll
        for (int i = 0; i < 24; i++) { float d = v[i] - m; ss += d * d; }
#pragma unroll
        for (int o = 16; o; o >>= 1) ss += __shfl_xor_sync(0xffffffffu, ss, o);
        float inv = rsqrtf(ss * (1.0f / CA) + 1e-5f);
        float* op = alnr + (size_t)row * CA;
#pragma unroll
        for (int i = 0; i < 24; i++)
            op[lane + 32 * i] = (v[i] - m) * inv;
    } else {
        int b = bx - 1024;
        const float* src;
        uint32_t* dst;
        int local;
        if (b < 2880) {
            int seg = b / 576;
            local = b - seg * 576;
            src = (seg == 0) ? wq : (seg == 1) ? wk : (seg == 2) ? wv
                : (seg == 3) ? wg : wo;
            dst = wt + (size_t)seg * W768;
        } else {
            local = b - 2880;
            src = wlast;
            dst = wt + (size_t)5 * W768;
        }
        int idx = local * 256 + threadIdx.x;
        float4 vsrc = ((const float4*)src)[idx];
        uint4 vd;
        vd.x = f2tf(vsrc.x); vd.y = f2tf(vsrc.y);
        vd.z = f2tf(vsrc.z); vd.w = f2tf(vsrc.w);
        ((uint4*)dst)[idx] = vd;
    }
}

// ---------------- cp.async TF32 GEMM: BM=128 BN=128 BK=16, 3 stages (R10) ------------
#define ASTRIDE 20
#define STAGE_WORDS (128 * ASTRIDE + 16 * 136)   // 4736
#define GEMM_SMEM (3 * STAGE_WORDS * 4)          // 56832 B

__device__ __forceinline__ void issue_tile(uint32_t sbase,
                                           const uint32_t* __restrict__ A,
                                           const uint32_t* __restrict__ B,
                                           int K, int k0, int row0, int col0, int tid)
{
    int arow = tid >> 1, ac = (tid & 1) * 2;
    const uint32_t* asrc = A + (size_t)(row0 + arow) * K + k0 + ac * 4;
    uint32_t adst = sbase + (arow * ASTRIDE + ac * 4) * 4;
    cp16(adst, asrc);
    cp16(adst + 16, asrc + 4);
    int brow = tid >> 4, bc = (tid & 15) * 2;
    const uint32_t* bsrc = B + (size_t)(k0 + brow) * 768 + col0 + bc * 4;
    uint32_t bdst = sbase + (128 * ASTRIDE + brow * 136 + bc * 4) * 4;
    cp16(bdst, bsrc);
    cp16(bdst + 16, bsrc + 4);
}

__device__ __forceinline__ void gemm_ca_body(const uint32_t* __restrict__ A,
                                             const uint32_t* __restrict__ B,
                                             const float* __restrict__ bias,
                                             const float* __restrict__ emul,
                                             float* __restrict__ C,
                                             int K, int act, int bx, int by)
{
    extern __shared__ uint32_t gsm[];
    uint32_t sbase = (uint32_t)__cvta_generic_to_shared(gsm);

    int tid = threadIdx.x;
    int wid = tid >> 5, lane = tid & 31;
    int warp_m = wid >> 2, warp_n = wid & 3;
    int group = lane >> 2, tg = lane & 3;
    int row0 = by * 128;
    int col0 = bx * 128;

    float acc[4][4][4];
#pragma unroll
    for (int mt = 0; mt < 4; mt++)
#pragma unroll
        for (int nt = 0; nt < 4; nt++)
#pragma unroll
            for (int r = 0; r < 4; r++) acc[mt][nt][r] = 0.f;

    int kt = K >> 4;
    issue_tile(sbase, A, B, K, 0, row0, col0, tid);
    CP_COMMIT();
    issue_tile(sbase + STAGE_WORDS * 4, A, B, K, 16, row0, col0, tid);
    CP_COMMIT();

    int stage = 0;
    for (int it = 0; it < kt; it++) {
        CP_WAIT1();
        __syncthreads();
        const uint32_t* As = gsm + stage * STAGE_WORDS;
        const uint32_t* Bs = As + 128 * ASTRIDE;

#pragma unroll
        for (int kc = 0; kc < 2; kc++) {
            int kb = kc * 8;
            uint32_t afr[4][4];
#pragma unroll
            for (int mt = 0; mt < 4; mt++) {
                int m = (warp_m * 64 + mt * 16 + group) * ASTRIDE;
                afr[mt][0] = As[m + kb + tg];
                afr[mt][1] = As[m + 8 * ASTRIDE + kb + tg];
                afr[mt][2] = As[m + kb + tg + 4];
                afr[mt][3] = As[m + 8 * ASTRIDE + kb + tg + 4];
            }
            uint32_t bfr[4][2];
#pragma unroll
            for (int nt = 0; nt < 4; nt++) {
                int n = warp_n * 32 + nt * 8 + group;
                bfr[nt][0] = Bs[(kb + tg) * 136 + n];
                bfr[nt][1] = Bs[(kb + tg + 4) * 136 + n];
            }
#pragma unroll
            for (int mt = 0; mt < 4; mt++)
#pragma unroll
                for (int nt = 0; nt < 4; nt++)
                    mma8(acc[mt][nt], afr[mt], bfr[nt]);
        }

        if (it + 2 < kt) {
            int nst = stage + 2; if (nst >= 3) nst -= 3;
            issue_tile(sbase + nst * STAGE_WORDS * 4, A, B, K,
                       (it + 2) * 16, row0, col0, tid);
        }
        CP_COMMIT();
        stage = stage + 1; if (stage == 3) stage = 0;
    }

#pragma unroll
    for (int mt = 0; mt < 4; mt++) {
#pragma unroll
        for (int nt = 0; nt < 4; nt++) {
            int col = col0 + warp_n * 32 + nt * 8 + tg * 2;
            float b0 = bias ? bias[col]     : 0.f;
            float b1 = bias ? bias[col + 1] : 0.f;
#pragma unroll
            for (int half = 0; half < 2; half++) {
                int row = row0 + warp_m * 64 + mt * 16 + group + half * 8;
                float v0 = acc[mt][nt][half * 2 + 0] + b0;
                float v1 = acc[mt][nt][half * 2 + 1] + b1;
                if (act == 1) {
                    v0 = 1.f / (1.f + expf(-v0));
                    v1 = 1.f / (1.f + expf(-v1));
                }
                if (emul) {
                    v0 *= emul[(size_t)row * 768 + col];
                    v1 *= emul[(size_t)row * 768 + col + 1];
                }
                float2 r = make_float2(v0, v1);
                *(float2*)&C[(size_t)row * 768 + col] = r;
            }
        }
    }
}

__global__ __launch_bounds__(256) void tgemm_ca(const uint32_t* __restrict__ A,
                                                const uint32_t* __restrict__ B,
                                                const float* __restrict__ bias,
                                                const float* __restrict__ emul,
                                                float* __restrict__ C,
                                                int K, int act)
{
    gemm_ca_body(A, B, bias, emul, C, K, act, blockIdx.x, blockIdx.y);
}

// ---------------- bias2 body (LN(z)*gamma @ wz as fused LN + TF32 GEMM) --------------
#define ZAS 132
#define ZBS 24
#define BIAS2_SMEM ((128 * ZAS + 128 * ZBS) * 4)   // 79872 B

__device__ __forceinline__ void bias2_body(int blk,
                                           const float* __restrict__ z,
                                           const float* __restrict__ gamma,
                                           const float* __restrict__ wz,
                                           float* __restrict__ out)
{
    extern __shared__ uint32_t dyn[];
    uint32_t* As = dyn;
    uint32_t* Bs = dyn + 128 * ZAS;
    float*    st = (float*)dyn;

    int tid = threadIdx.x;
    int wid = tid >> 5, lane = tid & 31;

    for (int idx = tid; idx < 2048; idx += 256) {
        int c = idx >> 4, h = idx & 15;
        Bs[c * ZBS + h] = f2tf(wz[idx]);
    }

    float4 g4 = *(const float4*)(gamma + lane * 4);

    const float* zbase = z + ((size_t)blk * 128 + wid) * CZ + lane * 4;
    float4 rv[16];
#pragma unroll
    for (int i = 0; i < 16; i++)
        rv[i] = *(const float4*)(zbase + (size_t)i * 8 * CZ);

#pragma unroll
    for (int i = 0; i < 16; i++) {
        int r = wid + 8 * i;
        float4 x = rv[i];
        float sum = x.x + x.y + x.z + x.w;
#pragma unroll
        for (int o = 16; o; o >>= 1) sum += __shfl_xor_sync(0xffffffffu, sum, o);
        float m = sum * (1.0f / CZ);
        float d0 = x.x - m, d1 = x.y - m, d2 = x.z - m, d3 = x.w - m;
        float ss = d0 * d0 + d1 * d1 + d2 * d2 + d3 * d3;
#pragma unroll
        for (int o = 16; o; o >>= 1) ss += __shfl_xor_sync(0xffffffffu, ss, o);
        float inv = rsqrtf(ss * (1.0f / CZ) + 1e-5f);
        uint4 pk;
        pk.x = f2tf(d0 * inv * g4.x);
        pk.y = f2tf(d1 * inv * g4.y);
        pk.z = f2tf(d2 * inv * g4.z);
        pk.w = f2tf(d3 * inv * g4.w);
        *(uint4*)&As[r * ZAS + lane * 4] = pk;
    }
    __syncthreads();

    int group = lane >> 2, tg = lane & 3;
    int m0 = wid * 16;
    float acc[2][4];
#pragma unroll
    for (int nt = 0; nt < 2; nt++)
#pragma unroll
        for (int r = 0; r < 4; r++) acc[nt][r] = 0.f;

#pragma unroll
    for (int ks = 0; ks < 16; ks++) {
        int kb = ks * 8;
        uint32_t a[4];
        a[0] = As[(m0 + group)     * ZAS + kb + tg];
        a[1] = As[(m0 + group + 8) * ZAS + kb + tg];
        a[2] = As[(m0 + group)     * ZAS + kb + tg + 4];
        a[3] = As[(m0 + group + 8) * ZAS + kb + tg + 4];
        uint32_t b0[2], b1[2];
        b0[0] = Bs[(kb + tg)     * ZBS + group];
        b0[1] = Bs[(kb + tg + 4) * ZBS + group];
        b1[0] = Bs[(kb + tg)     * ZBS + 8 + group];
        b1[1] = Bs[(kb + tg + 4) * ZBS + 8 + group];
        mma8(acc[0], a, b0);
        mma8(acc[1], a, b1);
    }
    __syncthreads();

#pragma unroll
    for (int nt = 0; nt < 2; nt++)
#pragma unroll
        for (int half = 0; half < 2; half++) {
            int m  = m0 + group + half * 8;
            int h0 = nt * 8 + tg * 2;
            st[h0       * 129 + m] = acc[nt][half * 2 + 0];
            st[(h0 + 1) * 129 + m] = acc[nt][half * 2 + 1];
        }
    __syncthreads();

    int wwin = blk >> 5;
    int rembase = (blk & 31) * 128;
#pragma unroll
    for (int i = 0; i < 8; i++) {
        int idx = tid + 256 * i;
        int h = idx >> 7, m = idx & 127;
        out[((size_t)(wwin * 16 + h)) * 4096 + rembase + m] = st[h * 129 + m];
    }
}

// ---------------- FAT kernel: bias2 (4096) ∥ qkvg+wlast GEMMs (960) ------------------
// Resource union keeps BOTH paths at 2 CTAs/SM: regs ~114 (58K/64K), smem 79.9KB (160/227KB).
#define FATQ 960
#define FATN 5056
__global__ __launch_bounds__(256) void fat2_kernel(const float* __restrict__ z,
                                                   const float* __restrict__ lnzg,
                                                   const float* __restrict__ wz,
                                                   float* __restrict__ bias_out,
                                                   const uint32_t* __restrict__ alnt,
                                                   const uint32_t* __restrict__ stf,
                                                   const uint32_t* __restrict__ wt,
                                                   const float* __restrict__ bq,
                                                   const float* __restrict__ bg,
                                                   const float* __restrict__ blast,
                                                   float* __restrict__ q,
                                                   float* __restrict__ k,
                                                   float* __restrict__ v,
                                                   float* __restrict__ g,
                                                   float* __restrict__ t2)
{
    int idx = blockIdx.x;
    int q_lo = (int)(((long long)idx       * FATQ) / FATN);
    int q_hi = (int)(((long long)(idx + 1) * FATQ) / FATN);
    if (q_hi > q_lo) {
        int qid = q_lo;                 // 0..959
        int bx  = qid % 6;
        int tmp = qid / 6;
        int by  = tmp % 32;
        int zi  = tmp / 32;             // 0..4
        if (zi < 4) {
            const uint32_t* B = wt + (size_t)zi * W768;
            const float* bias = (zi == 0) ? bq : (zi == 3) ? bg : nullptr;
            float* C          = (zi == 0) ? q  : (zi == 1) ? k  : (zi == 2) ? v  : g;
            int act           = (zi == 3) ? 1 : 0;
            gemm_ca_body(alnt, B, bias, nullptr, C, 768, act, bx, by);
        } else {
            gemm_ca_body(stf, wt + (size_t)5 * W768, blast, nullptr, t2, 384, 1,
                         bx, by);
        }
    } else {
        int bid = idx - q_lo;           // 0..4095
        bias2_body(bid, z, lnzg, wz, bias_out);
    }
}

// ---------------- dual-B adaln GEMM (BN=64, writes tf32 aln) ----------------
#define AS_STRIDE 136
#define BS_STRIDE 72
__global__ __launch_bounds__(256) void adaln_kernel(const float* __restrict__ sln,
                                                    const float* __restrict__ ws,
                                                    const float* __restrict__ wskip,
                                                    const float* __restrict__ bs,
                                                    const float* __restrict__ alnr,
                                                    uint32_t* __restrict__ alnt)
{
    __shared__ uint32_t As [16 * AS_STRIDE];
    __shared__ uint32_t Bs1[16 * BS_STRIDE];
    __shared__ uint32_t Bs2[16 * BS_STRIDE];

    const int K = 384;
    int tid = threadIdx.x;
    int wid = tid >> 5, lane = tid & 31;
    int warp_m = wid >> 1, warp_n = wid & 1;
    int group = lane >> 2, tg = lane & 3;
    int row0 = blockIdx.y * 128;
    int col0 = blockIdx.x * 64;

    int arow = tid >> 1, akp = (tid & 1) * 8;
    int brow = tid >> 4, bcol = (tid & 15) * 4;

    const float* Abase = sln + (size_t)(row0 + arow) * K;

    float acc1[2][4][4], acc2[2][4][4];
#pragma unroll
    for (int mt = 0; mt < 2; mt++)
#pragma unroll
        for (int nt = 0; nt < 4; nt++)
#pragma unroll
            for (int r = 0; r < 4; r++) { acc1[mt][nt][r] = 0.f; acc2[mt][nt][r] = 0.f; }

    {
        float4 va0 = *(const float4*)(Abase + akp);
        float4 va1 = *(const float4*)(Abase + akp + 4);
        float4 vb1 = *(const float4*)(ws    + (size_t)brow * 768 + col0 + bcol);
        float4 vb2 = *(const float4*)(wskip + (size_t)brow * 768 + col0 + bcol);
        float av[8] = {va0.x, va0.y, va0.z, va0.w, va1.x, va1.y, va1.z, va1.w};
#pragma unroll
        for (int i = 0; i < 8; i++) As[(akp + i) * AS_STRIDE + arow] = f2tf(av[i]);
        float b1v[4] = {vb1.x, vb1.y, vb1.z, vb1.w};
        float b2v[4] = {vb2.x, vb2.y, vb2.z, vb2.w};
#pragma unroll
        for (int i = 0; i < 4; i++) {
            Bs1[brow * BS_STRIDE + bcol + i] = f2tf(b1v[i]);
            Bs2[brow * BS_STRIDE + bcol + i] = f2tf(b2v[i]);
        }
    }

    for (int k0 = 0; k0 < K; k0 += 16) {
        __syncthreads();
        bool has_next = (k0 + 16) < K;
        float4 va0, va1, vb1, vb2;
        if (has_next) {
            va0 = *(const float4*)(Abase + k0 + 16 + akp);
            va1 = *(const float4*)(Abase + k0 + 16 + akp + 4);
            vb1 = *(const float4*)(ws    + (size_t)(k0 + 16 + brow) * 768 + col0 + bcol);
            vb2 = *(const float4*)(wskip + (size_t)(k0 + 16 + brow) * 768 + col0 + bcol);
        }

#pragma unroll
        for (int kc = 0; kc < 2; kc++) {
            int kb = kc * 8;
            uint32_t afr[2][4];
#pragma unroll
            for (int mt = 0; mt < 2; mt++) {
                int m = warp_m * 32 + mt * 16 + group;
                afr[mt][0] = As[(kb + tg) * AS_STRIDE + m];
                afr[mt][1] = As[(kb + tg) * AS_STRIDE + m + 8];
                afr[mt][2] = As[(kb + tg + 4) * AS_STRIDE + m];
                afr[mt][3] = As[(kb + tg + 4) * AS_STRIDE + m + 8];
            }
#pragma unroll
            for (int nt = 0; nt < 4; nt++) {
                int n = warp_n * 32 + nt * 8 + group;
                uint32_t b1[2], b2[2];
                b1[0] = Bs1[(kb + tg) * BS_STRIDE + n];
                b1[1] = Bs1[(kb + tg + 4) * BS_STRIDE + n];
                b2[0] = Bs2[(kb + tg) * BS_STRIDE + n];
                b2[1] = Bs2[(kb + tg + 4) * BS_STRIDE + n];
#pragma unroll
                for (int mt = 0; mt < 2; mt++) {
                    mma8(acc1[mt][nt], afr[mt], b1);
                    mma8(acc2[mt][nt], afr[mt], b2);
                }
            }
        }

        __syncthreads();
        if (has_next) {
            float av[8] = {va0.x, va0.y, va0.z, va0.w, va1.x, va1.y, va1.z, va1.w};
#pragma unroll
            for (int i = 0; i < 8; i++) As[(akp + i) * AS_STRIDE + arow] = f2tf(av[i]);
            float b1v[4] = {vb1.x, vb1.y, vb1.z, vb1.w};
            float b2v[4] = {vb2.x, vb2.y, vb2.z, vb2.w};
#pragma unroll
            for (int i = 0; i < 4; i++) {
                Bs1[brow * BS_STRIDE + bcol + i] = f2tf(b1v[i]);
                Bs2[brow * BS_STRIDE + bcol + i] = f2tf(b2v[i]);
            }
        }
    }

#pragma unroll
    for (int mt = 0; mt < 2; mt++) {
#pragma unroll
        for (int nt = 0; nt < 4; nt++) {
            int col = col0 + warp_n * 32 + nt * 8 + tg * 2;
            float b0 = bs[col], b1 = bs[col + 1];
#pragma unroll
            for (int half = 0; half < 2; half++) {
                int row = row0 + warp_m * 32 + mt * 16 + group + half * 8;
                float s0 = 1.f / (1.f + expf(-(acc1[mt][nt][half * 2 + 0] + b0)));
                float s1 = 1.f / (1.f + expf(-(acc1[mt][nt][half * 2 + 1] + b1)));
                float r0 = s0 * alnr[(size_t)row * 768 + col]     + acc2[mt][nt][half * 2 + 0];
                float r1 = s1 * alnr[(size_t)row * 768 + col + 1] + acc2[mt][nt][half * 2 + 1];
                uint2 rr;
                rr.x = f2tf(r0);
                rr.y = f2tf(r1);
                *(uint2*)&alnt[(size_t)row * 768 + col] = rr;
            }
        }
    }
}

// ---------------- local attention (lean) -> writes tf32(g * o) ----------------
#define ATTN_SMEM ((32 * 48 + 2 * 128 * 52) * 4)
__global__ __launch_bounds__(256) void attn_kernel(const float* __restrict__ q,
                                                   const float* __restrict__ k,
                                                   const float* __restrict__ v,
                                                   const float* __restrict__ bias,
                                                   const float* __restrict__ gate,
                                                   uint32_t* __restrict__ t1)
{
    extern __shared__ float sm[];
    float* qs = sm;
    float* ks = sm + 32 * 48;
    float* vs = ks + 128 * 52;
    int w = blockIdx.x, h = blockIdx.y;
    int tid = threadIdx.x;

    {
        const float* qbase = q + (size_t)w * 32 * CA + h * 48;
#pragma unroll
        for (int it = 0; it < 2; it++) {
            int i = tid + it * 256;
            if (i < 384) {
                int r = i / 12, c = i - r * 12;
                *(float4*)&qs[r * 48 + c * 4] =
                    *(const float4*)(qbase + (size_t)r * CA + c * 4);
            }
        }
    }
    {
        int r = tid >> 1, half = tid & 1;
        int tok = w * 32 - 48 + r;
        tok = tok < 0 ? 0 : (tok > 4095 ? 4095 : tok);
        const float4* kg = (const float4*)(k + (size_t)tok * CA + h * 48) + half * 6;
        const float4* vg = (const float4*)(v + (size_t)tok * CA + h * 48) + half * 6;
        float* kd = &ks[r * 52 + half * 24];
        float* vd = &vs[r * 52 + half * 24];
#pragma unroll
        for (int j = 0; j < 6; j++) {
            *(float4*)&kd[j * 4] = kg[j];
            *(float4*)&vd[j * 4] = vg[j];
        }
    }
    __syncthreads();

    int qi = tid >> 3, g = tid & 7;
    float4 qreg[12];
#pragma unroll
    for (int j = 0; j < 12; j++) qreg[j] = *(const float4*)&qs[qi * 48 + 4 * j];

    const float scale = 0.14433756729740643f;
    float sc[16];
    const float* bp = bias + ((size_t)(w * 16 + h) * 32 + qi) * 128;
#pragma unroll
    for (int jj = 0; jj < 16; jj++) {
        int kj = g + 8 * jj;
        int tok = w * 32 - 48 + kj;
        if (tok < 0 || tok >= 4096) { sc[jj] = -1e9f; continue; }
        const float4* kp = (const float4*)&ks[kj * 52];
        float a0 = 0.f, a1 = 0.f, a2 = 0.f, a3 = 0.f;
#pragma unroll
        for (int j = 0; j < 12; j++) {
            float4 kv = kp[j];
            a0 += qreg[j].x * kv.x;
            a1 += qreg[j].y * kv.y;
            a2 += qreg[j].z * kv.z;
            a3 += qreg[j].w * kv.w;
        }
        sc[jj] = ((a0 + a1) + (a2 + a3)) * scale + bp[kj];
    }
    float mx = sc[0];
#pragma unroll
    for (int jj = 1; jj < 16; jj++) mx = fmaxf(mx, sc[jj]);
#pragma unroll
    for (int o2 = 1; o2 < 8; o2 <<= 1) mx = fmaxf(mx, __shfl_xor_sync(0xffffffffu, mx, o2));
    float sum = 0.f;
#pragma unroll
    for (int jj = 0; jj < 16; jj++) { sc[jj] = __expf(sc[jj] - mx); sum += sc[jj]; }
#pragma unroll
    for (int o2 = 1; o2 < 8; o2 <<= 1) sum += __shfl_xor_sync(0xffffffffu, sum, o2);
    float inv = 1.f / sum;

    float oa[48];
#pragma unroll
    for (int d = 0; d < 48; d++) oa[d] = 0.f;
#pragma unroll
    for (int jj = 0; jj < 16; jj++) {
        float p = sc[jj] * inv;
        const float4* vp = (const float4*)&vs[(g + 8 * jj) * 52];
#pragma unroll
        for (int j = 0; j < 12; j++) {
            float4 vv = vp[j];
            oa[4 * j + 0] += p * vv.x; oa[4 * j + 1] += p * vv.y;
            oa[4 * j + 2] += p * vv.z; oa[4 * j + 3] += p * vv.w;
        }
    }
#pragma unroll
    for (int o2 = 1; o2 < 8; o2 <<= 1)
#pragma unroll
        for (int d = 0; d < 48; d++)
            oa[d] += __shfl_xor_sync(0xffffffffu, oa[d], o2);

    size_t rowbase = (size_t)(w * 32 + qi) * CA + h * 48;
#pragma unroll
    for (int j = 0; j < 6; j++) {
        int d = g * 6 + j;
        float gv = gate[rowbase + d];
        t1[rowbase + d] = f2tf(gv * oa[d]);
    }
}

// ---------------- launch ----------------
extern "C" void kernel_launch(void* const* d_in, const int* in_sizes, int n_in,
                              void* d_out, int out_size)
{
    const float* a        = (const float*)d_in[0];
    const float* s        = (const float*)d_in[1];
    const float* z        = (const float*)d_in[2];
    const float* gamma_s  = (const float*)d_in[3];
    const float* ws       = (const float*)d_in[4];
    const float* bs       = (const float*)d_in[5];
    const float* wskip    = (const float*)d_in[6];
    const float* lnzg     = (const float*)d_in[7];
    const float* wz       = (const float*)d_in[8];
    const float* wq       = (const float*)d_in[9];
    const float* bq       = (const float*)d_in[10];
    const float* wk       = (const float*)d_in[11];
    const float* wv       = (const float*)d_in[12];
    const float* wg       = (const float*)d_in[13];
    const float* bg       = (const float*)d_in[14];
    const float* wo       = (const float*)d_in[15];
    const float* bo       = (const float*)d_in[16];
    const float* wlast    = (const float*)d_in[17];
    const float* blast    = (const float*)d_in[18];
    float* out = (float*)d_out;

    float *p_sln, *p_alnr, *p_t2, *p_q, *p_k, *p_v, *p_g, *p_bias;
    uint32_t *p_stf, *p_alnt, *p_t1t, *p_wt;
    cudaGetSymbolAddress((void**)&p_sln,  g_sln);
    cudaGetSymbolAddress((void**)&p_stf,  g_stf);
    cudaGetSymbolAddress((void**)&p_alnr, g_alnr);
    cudaGetSymbolAddress((void**)&p_alnt, g_alnt);
    cudaGetSymbolAddress((void**)&p_t2,   g_t2);
    cudaGetSymbolAddress((void**)&p_q,    g_q);
    cudaGetSymbolAddress((void**)&p_k,    g_k);
    cudaGetSymbolAddress((void**)&p_v,    g_v);
    cudaGetSymbolAddress((void**)&p_g,    g_g);
    cudaGetSymbolAddress((void**)&p_t1t,  g_t1t);
    cudaGetSymbolAddress((void**)&p_bias, g_bias);
    cudaGetSymbolAddress((void**)&p_wt,   g_wt);

    cudaFuncSetAttribute(attn_kernel, cudaFuncAttributeMaxDynamicSharedMemorySize, ATTN_SMEM);
    cudaFuncSetAttribute(tgemm_ca,    cudaFuncAttributeMaxDynamicSharedMemorySize, GEMM_SMEM);
    cudaFuncSetAttribute(fat2_kernel, cudaFuncAttributeMaxDynamicSharedMemorySize, BIAS2_SMEM);

    // 0: LN(s)+stf / LN(a) / weight tf32 conversion — all independent
    ln_fused_kernel<<<4192, 256>>>(s, gamma_s, p_sln, p_stf, a, p_alnr,
                                   wq, wk, wv, wg, wo, wlast, p_wt);

    // 1: aln = sigmoid(sln@ws + bs) * ln(a) + sln@wskip  (writes tf32 aln)
    adaln_kernel<<<dim3(12, 32), 256>>>(p_sln, ws, wskip, bs, p_alnr, p_alnt);

    // 2: FAT — pair-bias (z-path) overlapped with QKVG + wlast GEMMs
    fat2_kernel<<<FATN, 256, BIAS2_SMEM>>>(z, lnzg, wz, p_bias,
                                           p_alnt, p_stf, p_wt, bq, bg, blast,
                                           p_q, p_k, p_v, p_g, p_t2);

    // 3: attention -> t1 = tf32(g * o)
    attn_kernel<<<dim3(128, 16), 256, ATTN_SMEM>>>(p_q, p_k, p_v, p_bias, p_g, p_t1t);

    // 4: out = (t1 @ wo + bo) * t2
    tgemm_ca<<<dim3(6, 32), 256, GEMM_SMEM>>>(p_t1t, p_wt + (size_t)4 * W768,
                                              bo, p_t2, out, 768, 0);
}

// round 16
// speedup vs baseline: 1.3166x; 1.0618x over previous
#include <cuda_runtime.h>
#include <math.h>
#include <stdint.h>

// Problem constants
#define N_TOK 4096
#define CA 768
#define CS 384
#define CZ 128
#define NH 16
#define HD 48

#define W768 589824     // 768*768
#define W384 294912     // 384*768

// ---------------- scratch ----------------
__device__ __align__(16) float    g_sln [N_TOK * CS];
__device__ __align__(16) uint32_t g_stf [N_TOK * CS];     // tf32(s)
__device__ __align__(16) float    g_alnr[N_TOK * CA];
__device__ __align__(16) uint32_t g_alnt[N_TOK * CA];     // tf32(aln)
__device__ __align__(16) float    g_t2  [N_TOK * CA];     // sigmoid(s@wlast+blast)
__device__ __align__(16) float    g_q   [N_TOK * CA];
__device__ __align__(16) float    g_k   [N_TOK * CA];
__device__ __align__(16) float    g_v   [N_TOK * CA];
__device__ __align__(16) float    g_g   [N_TOK * CA];
__device__ __align__(16) uint32_t g_t1t [N_TOK * CA];     // tf32(g*o)
__device__ __align__(16) float    g_bias[NH * 128 * 32 * 128];
__device__ __align__(16) uint32_t g_wt  [5 * W768 + W384]; // wq wk wv wg wo | wlast

// ---------------- TF32 helpers ----------------
__device__ __forceinline__ uint32_t f2tf(float x)
{
    uint32_t r;
    asm("cvt.rna.tf32.f32 %0, %1;" : "=r"(r) : "f"(x));
    return r;
}

__device__ __forceinline__ void mma8(float* c, const uint32_t* a, const uint32_t* b)
{
    asm volatile("mma.sync.aligned.m16n8k8.row.col.f32.tf32.tf32.f32 "
                 "{%0,%1,%2,%3}, {%4,%5,%6,%7}, {%8,%9}, {%0,%1,%2,%3};"
                 : "+f"(c[0]), "+f"(c[1]), "+f"(c[2]), "+f"(c[3])
                 : "r"(a[0]), "r"(a[1]), "r"(a[2]), "r"(a[3]),
                   "r"(b[0]), "r"(b[1]));
}

__device__ __forceinline__ void cp16(uint32_t dst, const void* src)
{
    asm volatile("cp.async.cg.shared.global [%0], [%1], 16;" :: "r"(dst), "l"(src));
}
#define CP_COMMIT() asm volatile("cp.async.commit_group;")
#define CP_WAIT1()  asm volatile("cp.async.wait_group 1;")

// ---------------- fused LN + weight-convert kernel ----------------
__global__ __launch_bounds__(256) void ln_fused_kernel(const float* __restrict__ s,
                                                       const float* __restrict__ gamma,
                                                       float* __restrict__ sln,
                                                       uint32_t* __restrict__ stf,
                                                       const float* __restrict__ a,
                                                       float* __restrict__ alnr,
                                                       const float* __restrict__ wq,
                                                       const float* __restrict__ wk,
                                                       const float* __restrict__ wv,
                                                       const float* __restrict__ wg,
                                                       const float* __restrict__ wo,
                                                       const float* __restrict__ wlast,
                                                       uint32_t* __restrict__ wt)
{
    int lane = threadIdx.x & 31;
    int bx = blockIdx.x;
    if (bx < 512) {
        int row = bx * 8 + (threadIdx.x >> 5);
        const float* x = s + (size_t)row * CS;
        float v[12];
        float sum = 0.f;
#pragma unroll
        for (int i = 0; i < 12; i++) { v[i] = x[lane + 32 * i]; sum += v[i]; }
#pragma unroll
        for (int o = 16; o; o >>= 1) sum += __shfl_xor_sync(0xffffffffu, sum, o);
        float m = sum * (1.0f / CS);
        float ss = 0.f;
#pragma unroll
        for (int i = 0; i < 12; i++) { float d = v[i] - m; ss += d * d; }
#pragma unroll
        for (int o = 16; o; o >>= 1) ss += __shfl_xor_sync(0xffffffffu, ss, o);
        float inv = rsqrtf(ss * (1.0f / CS) + 1e-5f);
        float* op = sln + (size_t)row * CS;
        uint32_t* op2 = stf + (size_t)row * CS;
#pragma unroll
        for (int i = 0; i < 12; i++) {
            op [lane + 32 * i] = (v[i] - m) * inv * gamma[lane + 32 * i];
            op2[lane + 32 * i] = f2tf(v[i]);
        }
    } else if (bx < 1024) {
        int row = (bx - 512) * 8 + (threadIdx.x >> 5);
        const float* x = a + (size_t)row * CA;
        float v[24];
        float sum = 0.f;
#pragma unroll
        for (int i = 0; i < 24; i++) { v[i] = x[lane + 32 * i]; sum += v[i]; }
#pragma unroll
        for (int o = 16; o; o >>= 1) sum += __shfl_xor_sync(0xffffffffu, sum, o);
        float m = sum * (1.0f / CA);
        float ss = 0.f;
#pragma unroll
        for (int i = 0; i < 24; i++) { float d = v[i] - m; ss += d * d; }
#pragma unroll
        for (int o = 16; o; o >>= 1) ss += __shfl_xor_sync(0xffffffffu, ss, o);
        float inv = rsqrtf(ss * (1.0f / CA) + 1e-5f);
        float* op = alnr + (size_t)row * CA;
#pragma unroll
        for (int i = 0; i < 24; i++)
            op[lane + 32 * i] = (v[i] - m) * inv;
    } else {
        int b = bx - 1024;
        const float* src;
        uint32_t* dst;
        int local;
        if (b < 2880) {
            int seg = b / 576;
            local = b - seg * 576;
            src = (seg == 0) ? wq : (seg == 1) ? wk : (seg == 2) ? wv
                : (seg == 3) ? wg : wo;
            dst = wt + (size_t)seg * W768;
        } else {
            local = b - 2880;
            src = wlast;
            dst = wt + (size_t)5 * W768;
        }
        int idx = local * 256 + threadIdx.x;
        float4 vsrc = ((const float4*)src)[idx];
        uint4 vd;
        vd.x = f2tf(vsrc.x); vd.y = f2tf(vsrc.y);
        vd.z = f2tf(vsrc.z); vd.w = f2tf(vsrc.w);
        ((uint4*)dst)[idx] = vd;
    }
}

// ---------------- cp.async TF32 GEMM: BM=128 BN=128 BK=16, 3 stages (R10) ------------
#define ASTRIDE 20
#define STAGE_WORDS (128 * ASTRIDE + 16 * 136)   // 4736
#define GEMM_SMEM (3 * STAGE_WORDS * 4)          // 56832 B

__device__ __forceinline__ void issue_tile(uint32_t sbase,
                                           const uint32_t* __restrict__ A,
                                           const uint32_t* __restrict__ B,
                                           int K, int k0, int row0, int col0, int tid)
{
    int arow = tid >> 1, ac = (tid & 1) * 2;
    const uint32_t* asrc = A + (size_t)(row0 + arow) * K + k0 + ac * 4;
    uint32_t adst = sbase + (arow * ASTRIDE + ac * 4) * 4;
    cp16(adst, asrc);
    cp16(adst + 16, asrc + 4);
    int brow = tid >> 4, bc = (tid & 15) * 2;
    const uint32_t* bsrc = B + (size_t)(k0 + brow) * 768 + col0 + bc * 4;
    uint32_t bdst = sbase + (128 * ASTRIDE + brow * 136 + bc * 4) * 4;
    cp16(bdst, bsrc);
    cp16(bdst + 16, bsrc + 4);
}

__device__ __forceinline__ void gemm_ca_body(const uint32_t* __restrict__ A,
                                             const uint32_t* __restrict__ B,
                                             const float* __restrict__ bias,
                                             const float* __restrict__ emul,
                                             float* __restrict__ C,
                                             int K, int act, int bx, int by)
{
    extern __shared__ uint32_t gsm[];
    uint32_t sbase = (uint32_t)__cvta_generic_to_shared(gsm);

    int tid = threadIdx.x;
    int wid = tid >> 5, lane = tid & 31;
    int warp_m = wid >> 2, warp_n = wid & 3;
    int group = lane >> 2, tg = lane & 3;
    int row0 = by * 128;
    int col0 = bx * 128;

    float acc[4][4][4];
#pragma unroll
    for (int mt = 0; mt < 4; mt++)
#pragma unroll
        for (int nt = 0; nt < 4; nt++)
#pragma unroll
            for (int r = 0; r < 4; r++) acc[mt][nt][r] = 0.f;

    int kt = K >> 4;
    issue_tile(sbase, A, B, K, 0, row0, col0, tid);
    CP_COMMIT();
    issue_tile(sbase + STAGE_WORDS * 4, A, B, K, 16, row0, col0, tid);
    CP_COMMIT();

    int stage = 0;
    for (int it = 0; it < kt; it++) {
        CP_WAIT1();
        __syncthreads();
        const uint32_t* As = gsm + stage * STAGE_WORDS;
        const uint32_t* Bs = As + 128 * ASTRIDE;

#pragma unroll
        for (int kc = 0; kc < 2; kc++) {
            int kb = kc * 8;
            uint32_t afr[4][4];
#pragma unroll
            for (int mt = 0; mt < 4; mt++) {
                int m = (warp_m * 64 + mt * 16 + group) * ASTRIDE;
                afr[mt][0] = As[m + kb + tg];
                afr[mt][1] = As[m + 8 * ASTRIDE + kb + tg];
                afr[mt][2] = As[m + kb + tg + 4];
                afr[mt][3] = As[m + 8 * ASTRIDE + kb + tg + 4];
            }
            uint32_t bfr[4][2];
#pragma unroll
            for (int nt = 0; nt < 4; nt++) {
                int n = warp_n * 32 + nt * 8 + group;
                bfr[nt][0] = Bs[(kb + tg) * 136 + n];
                bfr[nt][1] = Bs[(kb + tg + 4) * 136 + n];
            }
#pragma unroll
            for (int mt = 0; mt < 4; mt++)
#pragma unroll
                for (int nt = 0; nt < 4; nt++)
                    mma8(acc[mt][nt], afr[mt], bfr[nt]);
        }

        if (it + 2 < kt) {
            int nst = stage + 2; if (nst >= 3) nst -= 3;
            issue_tile(sbase + nst * STAGE_WORDS * 4, A, B, K,
                       (it + 2) * 16, row0, col0, tid);
        }
        CP_COMMIT();
        stage = stage + 1; if (stage == 3) stage = 0;
    }

#pragma unroll
    for (int mt = 0; mt < 4; mt++) {
#pragma unroll
        for (int nt = 0; nt < 4; nt++) {
            int col = col0 + warp_n * 32 + nt * 8 + tg * 2;
            float b0 = bias ? bias[col]     : 0.f;
            float b1 = bias ? bias[col + 1] : 0.f;
#pragma unroll
            for (int half = 0; half < 2; half++) {
                int row = row0 + warp_m * 64 + mt * 16 + group + half * 8;
                float v0 = acc[mt][nt][half * 2 + 0] + b0;
                float v1 = acc[mt][nt][half * 2 + 1] + b1;
                if (act == 1) {
                    v0 = 1.f / (1.f + expf(-v0));
                    v1 = 1.f / (1.f + expf(-v1));
                }
                if (emul) {
                    v0 *= emul[(size_t)row * 768 + col];
                    v1 *= emul[(size_t)row * 768 + col + 1];
                }
                float2 r = make_float2(v0, v1);
                *(float2*)&C[(size_t)row * 768 + col] = r;
            }
        }
    }
}

__global__ __launch_bounds__(256) void tgemm_ca(const uint32_t* __restrict__ A,
                                                const uint32_t* __restrict__ B,
                                                const float* __restrict__ bias,
                                                const float* __restrict__ emul,
                                                float* __restrict__ C,
                                                int K, int act)
{
    gemm_ca_body(A, B, bias, emul, C, K, act, blockIdx.x, blockIdx.y);
}

// ---------------- bias2 body (LN(z)*gamma @ wz as fused LN + TF32 GEMM) --------------
#define ZAS 132
#define ZBS 24
#define BIAS2_SMEM ((128 * ZAS + 128 * ZBS) * 4)   // 79872 B

__device__ __forceinline__ void bias2_body(int blk,
                                           const float* __restrict__ z,
                                           const float* __restrict__ gamma,
                                           const float* __restrict__ wz,
                                           float* __restrict__ out)
{
    extern __shared__ uint32_t dyn[];
    uint32_t* As = dyn;
    uint32_t* Bs = dyn + 128 * ZAS;
    float*    st = (float*)dyn;

    int tid = threadIdx.x;
    int wid = tid >> 5, lane = tid & 31;

    for (int idx = tid; idx < 2048; idx += 256) {
        int c = idx >> 4, h = idx & 15;
        Bs[c * ZBS + h] = f2tf(wz[idx]);
    }

    float4 g4 = *(const float4*)(gamma + lane * 4);

    const float* zbase = z + ((size_t)blk * 128 + wid) * CZ + lane * 4;
    float4 rv[16];
#pragma unroll
    for (int i = 0; i < 16; i++)
        rv[i] = *(const float4*)(zbase + (size_t)i * 8 * CZ);

#pragma unroll
    for (int i = 0; i < 16; i++) {
        int r = wid + 8 * i;
        float4 x = rv[i];
        float sum = x.x + x.y + x.z + x.w;
#pragma unroll
        for (int o = 16; o; o >>= 1) sum += __shfl_xor_sync(0xffffffffu, sum, o);
        float m = sum * (1.0f / CZ);
        float d0 = x.x - m, d1 = x.y - m, d2 = x.z - m, d3 = x.w - m;
        float ss = d0 * d0 + d1 * d1 + d2 * d2 + d3 * d3;
#pragma unroll
        for (int o = 16; o; o >>= 1) ss += __shfl_xor_sync(0xffffffffu, ss, o);
        float inv = rsqrtf(ss * (1.0f / CZ) + 1e-5f);
        uint4 pk;
        pk.x = f2tf(d0 * inv * g4.x);
        pk.y = f2tf(d1 * inv * g4.y);
        pk.z = f2tf(d2 * inv * g4.z);
        pk.w = f2tf(d3 * inv * g4.w);
        *(uint4*)&As[r * ZAS + lane * 4] = pk;
    }
    __syncthreads();

    int group = lane >> 2, tg = lane & 3;
    int m0 = wid * 16;
    float acc[2][4];
#pragma unroll
    for (int nt = 0; nt < 2; nt++)
#pragma unroll
        for (int r = 0; r < 4; r++) acc[nt][r] = 0.f;

#pragma unroll
    for (int ks = 0; ks < 16; ks++) {
        int kb = ks * 8;
        uint32_t a[4];
        a[0] = As[(m0 + group)     * ZAS + kb + tg];
        a[1] = As[(m0 + group + 8) * ZAS + kb + tg];
        a[2] = As[(m0 + group)     * ZAS + kb + tg + 4];
        a[3] = As[(m0 + group + 8) * ZAS + kb + tg + 4];
        uint32_t b0[2], b1[2];
        b0[0] = Bs[(kb + tg)     * ZBS + group];
        b0[1] = Bs[(kb + tg + 4) * ZBS + group];
        b1[0] = Bs[(kb + tg)     * ZBS + 8 + group];
        b1[1] = Bs[(kb + tg + 4) * ZBS + 8 + group];
        mma8(acc[0], a, b0);
        mma8(acc[1], a, b1);
    }
    __syncthreads();

#pragma unroll
    for (int nt = 0; nt < 2; nt++)
#pragma unroll
        for (int half = 0; half < 2; half++) {
            int m  = m0 + group + half * 8;
            int h0 = nt * 8 + tg * 2;
            st[h0       * 129 + m] = acc[nt][half * 2 + 0];
            st[(h0 + 1) * 129 + m] = acc[nt][half * 2 + 1];
        }
    __syncthreads();

    int wwin = blk >> 5;
    int rembase = (blk & 31) * 128;
#pragma unroll
    for (int i = 0; i < 8; i++) {
        int idx = tid + 256 * i;
        int h = idx >> 7, m = idx & 127;
        out[((size_t)(wwin * 16 + h)) * 4096 + rembase + m] = st[h * 129 + m];
    }
}

// ---------------- FAT kernel: bias2 (4096) ∥ qkvg+wlast GEMMs (960) ------------------
#define FATQ 960
#define FATN 5056
__global__ __launch_bounds__(256) void fat2_kernel(const float* __restrict__ z,
                                                   const float* __restrict__ lnzg,
                                                   const float* __restrict__ wz,
                                                   float* __restrict__ bias_out,
                                                   const uint32_t* __restrict__ alnt,
                                                   const uint32_t* __restrict__ stf,
                                                   const uint32_t* __restrict__ wt,
                                                   const float* __restrict__ bq,
                                                   const float* __restrict__ bg,
                                                   const float* __restrict__ blast,
                                                   float* __restrict__ q,
                                                   float* __restrict__ k,
                                                   float* __restrict__ v,
                                                   float* __restrict__ g,
                                                   float* __restrict__ t2)
{
    int idx = blockIdx.x;
    int q_lo = (int)(((long long)idx       * FATQ) / FATN);
    int q_hi = (int)(((long long)(idx + 1) * FATQ) / FATN);
    if (q_hi > q_lo) {
        int qid = q_lo;                 // 0..959
        int bx  = qid % 6;
        int tmp = qid / 6;
        int by  = tmp % 32;
        int zi  = tmp / 32;             // 0..4
        if (zi < 4) {
            const uint32_t* B = wt + (size_t)zi * W768;
            const float* bias = (zi == 0) ? bq : (zi == 3) ? bg : nullptr;
            float* C          = (zi == 0) ? q  : (zi == 1) ? k  : (zi == 2) ? v  : g;
            int act           = (zi == 3) ? 1 : 0;
            gemm_ca_body(alnt, B, bias, nullptr, C, 768, act, bx, by);
        } else {
            gemm_ca_body(stf, wt + (size_t)5 * W768, blast, nullptr, t2, 384, 1,
                         bx, by);
        }
    } else {
        int bid = idx - q_lo;           // 0..4095
        bias2_body(bid, z, lnzg, wz, bias_out);
    }
}

// ---------------- dual-B adaln GEMM (BN=64, writes tf32 aln) ----------------
#define AS_STRIDE 136
#define BS_STRIDE 72
__global__ __launch_bounds__(256) void adaln_kernel(const float* __restrict__ sln,
                                                    const float* __restrict__ ws,
                                                    const float* __restrict__ wskip,
                                                    const float* __restrict__ bs,
                                                    const float* __restrict__ alnr,
                                                    uint32_t* __restrict__ alnt)
{
    __shared__ uint32_t As [16 * AS_STRIDE];
    __shared__ uint32_t Bs1[16 * BS_STRIDE];
    __shared__ uint32_t Bs2[16 * BS_STRIDE];

    const int K = 384;
    int tid = threadIdx.x;
    int wid = tid >> 5, lane = tid & 31;
    int warp_m = wid >> 1, warp_n = wid & 1;
    int group = lane >> 2, tg = lane & 3;
    int row0 = blockIdx.y * 128;
    int col0 = blockIdx.x * 64;

    int arow = tid >> 1, akp = (tid & 1) * 8;
    int brow = tid >> 4, bcol = (tid & 15) * 4;

    const float* Abase = sln + (size_t)(row0 + arow) * K;

    float acc1[2][4][4], acc2[2][4][4];
#pragma unroll
    for (int mt = 0; mt < 2; mt++)
#pragma unroll
        for (int nt = 0; nt < 4; nt++)
#pragma unroll
            for (int r = 0; r < 4; r++) { acc1[mt][nt][r] = 0.f; acc2[mt][nt][r] = 0.f; }

    {
        float4 va0 = *(const float4*)(Abase + akp);
        float4 va1 = *(const float4*)(Abase + akp + 4);
        float4 vb1 = *(const float4*)(ws    + (size_t)brow * 768 + col0 + bcol);
        float4 vb2 = *(const float4*)(wskip + (size_t)brow * 768 + col0 + bcol);
        float av[8] = {va0.x, va0.y, va0.z, va0.w, va1.x, va1.y, va1.z, va1.w};
#pragma unroll
        for (int i = 0; i < 8; i++) As[(akp + i) * AS_STRIDE + arow] = f2tf(av[i]);
        float b1v[4] = {vb1.x, vb1.y, vb1.z, vb1.w};
        float b2v[4] = {vb2.x, vb2.y, vb2.z, vb2.w};
#pragma unroll
        for (int i = 0; i < 4; i++) {
            Bs1[brow * BS_STRIDE + bcol + i] = f2tf(b1v[i]);
            Bs2[brow * BS_STRIDE + bcol + i] = f2tf(b2v[i]);
        }
    }

    for (int k0 = 0; k0 < K; k0 += 16) {
        __syncthreads();
        bool has_next = (k0 + 16) < K;
        float4 va0, va1, vb1, vb2;
        if (has_next) {
            va0 = *(const float4*)(Abase + k0 + 16 + akp);
            va1 = *(const float4*)(Abase + k0 + 16 + akp + 4);
            vb1 = *(const float4*)(ws    + (size_t)(k0 + 16 + brow) * 768 + col0 + bcol);
            vb2 = *(const float4*)(wskip + (size_t)(k0 + 16 + brow) * 768 + col0 + bcol);
        }

#pragma unroll
        for (int kc = 0; kc < 2; kc++) {
            int kb = kc * 8;
            uint32_t afr[2][4];
#pragma unroll
            for (int mt = 0; mt < 2; mt++) {
                int m = warp_m * 32 + mt * 16 + group;
                afr[mt][0] = As[(kb + tg) * AS_STRIDE + m];
                afr[mt][1] = As[(kb + tg) * AS_STRIDE + m + 8];
                afr[mt][2] = As[(kb + tg + 4) * AS_STRIDE + m];
                afr[mt][3] = As[(kb + tg + 4) * AS_STRIDE + m + 8];
            }
#pragma unroll
            for (int nt = 0; nt < 4; nt++) {
                int n = warp_n * 32 + nt * 8 + group;
                uint32_t b1[2], b2[2];
                b1[0] = Bs1[(kb + tg) * BS_STRIDE + n];
                b1[1] = Bs1[(kb + tg + 4) * BS_STRIDE + n];
                b2[0] = Bs2[(kb + tg) * BS_STRIDE + n];
                b2[1] = Bs2[(kb + tg + 4) * BS_STRIDE + n];
#pragma unroll
                for (int mt = 0; mt < 2; mt++) {
                    mma8(acc1[mt][nt], afr[mt], b1);
                    mma8(acc2[mt][nt], afr[mt], b2);
                }
            }
        }

        __syncthreads();
        if (has_next) {
            float av[8] = {va0.x, va0.y, va0.z, va0.w, va1.x, va1.y, va1.z, va1.w};
#pragma unroll
            for (int i = 0; i < 8; i++) As[(akp + i) * AS_STRIDE + arow] = f2tf(av[i]);
            float b1v[4] = {vb1.x, vb1.y, vb1.z, vb1.w};
            float b2v[4] = {vb2.x, vb2.y, vb2.z, vb2.w};
#pragma unroll
            for (int i = 0; i < 4; i++) {
                Bs1[brow * BS_STRIDE + bcol + i] = f2tf(b1v[i]);
                Bs2[brow * BS_STRIDE + bcol + i] = f2tf(b2v[i]);
            }
        }
    }

#pragma unroll
    for (int mt = 0; mt < 2; mt++) {
#pragma unroll
        for (int nt = 0; nt < 4; nt++) {
            int col = col0 + warp_n * 32 + nt * 8 + tg * 2;
            float b0 = bs[col], b1 = bs[col + 1];
#pragma unroll
            for (int half = 0; half < 2; half++) {
                int row = row0 + warp_m * 32 + mt * 16 + group + half * 8;
                float s0 = 1.f / (1.f + expf(-(acc1[mt][nt][half * 2 + 0] + b0)));
                float s1 = 1.f / (1.f + expf(-(acc1[mt][nt][half * 2 + 1] + b1)));
                float r0 = s0 * alnr[(size_t)row * 768 + col]     + acc2[mt][nt][half * 2 + 0];
                float r1 = s1 * alnr[(size_t)row * 768 + col + 1] + acc2[mt][nt][half * 2 + 1];
                uint2 rr;
                rr.x = f2tf(r0);
                rr.y = f2tf(r1);
                *(uint2*)&alnt[(size_t)row * 768 + col] = rr;
            }
        }
    }
}

// ---------------- local attention: scalar scores + tensor-core P·V ----------------
// smem: qs[32*48] | ks[128*52] fp32 | vs[128*56] tf32 | ps[32*132] tf32
#define KSTR 52
#define VSTR 56
#define PSTR 132
#define ATTN_SMEM ((32 * 48 + 128 * KSTR + 128 * VSTR + 32 * PSTR) * 4)
__global__ __launch_bounds__(256) void attn_kernel(const float* __restrict__ q,
                                                   const float* __restrict__ k,
                                                   const float* __restrict__ v,
                                                   const float* __restrict__ bias,
                                                   const float* __restrict__ gate,
                                                   uint32_t* __restrict__ t1)
{
    extern __shared__ float sm[];
    float*    qs = sm;
    float*    ks = sm + 32 * 48;
    uint32_t* vs = (uint32_t*)(sm + 32 * 48 + 128 * KSTR);
    uint32_t* ps = vs + 128 * VSTR;
    int w = blockIdx.x, h = blockIdx.y;
    int tid = threadIdx.x;

    // Q staging
    {
        const float* qbase = q + (size_t)w * 32 * CA + h * 48;
#pragma unroll
        for (int it = 0; it < 2; it++) {
            int i = tid + it * 256;
            if (i < 384) {
                int r = i / 12, c = i - r * 12;
                *(float4*)&qs[r * 48 + c * 4] =
                    *(const float4*)(qbase + (size_t)r * CA + c * 4);
            }
        }
    }
    // K staging fp32, V staging tf32
    {
        int r = tid >> 1, half = tid & 1;
        int tok = w * 32 - 48 + r;
        tok = tok < 0 ? 0 : (tok > 4095 ? 4095 : tok);
        const float4* kg = (const float4*)(k + (size_t)tok * CA + h * 48) + half * 6;
        const float4* vg = (const float4*)(v + (size_t)tok * CA + h * 48) + half * 6;
        float*    kd = &ks[r * KSTR + half * 24];
        uint32_t* vd = &vs[r * VSTR + half * 24];
#pragma unroll
        for (int j = 0; j < 6; j++) {
            float4 kv = kg[j];
            *(float4*)&kd[j * 4] = kv;
            float4 vv = vg[j];
            uint4 u;
            u.x = f2tf(vv.x); u.y = f2tf(vv.y);
            u.z = f2tf(vv.z); u.w = f2tf(vv.w);
            *(uint4*)&vd[j * 4] = u;
        }
    }
    __syncthreads();

    int qi = tid >> 3, g = tid & 7;
    float4 qreg[12];
#pragma unroll
    for (int j = 0; j < 12; j++) qreg[j] = *(const float4*)&qs[qi * 48 + 4 * j];

    const float scale = 0.14433756729740643f;
    float sc[16];
    const float* bp = bias + ((size_t)(w * 16 + h) * 32 + qi) * 128;
#pragma unroll
    for (int jj = 0; jj < 16; jj++) {
        int kj = g + 8 * jj;
        int tok = w * 32 - 48 + kj;
        if (tok < 0 || tok >= 4096) { sc[jj] = -1e9f; continue; }
        const float4* kp = (const float4*)&ks[kj * KSTR];
        float a0 = 0.f, a1 = 0.f, a2 = 0.f, a3 = 0.f;
#pragma unroll
        for (int j = 0; j < 12; j++) {
            float4 kv = kp[j];
            a0 += qreg[j].x * kv.x;
            a1 += qreg[j].y * kv.y;
            a2 += qreg[j].z * kv.z;
            a3 += qreg[j].w * kv.w;
        }
        sc[jj] = ((a0 + a1) + (a2 + a3)) * scale + bp[kj];
    }
    float mx = sc[0];
#pragma unroll
    for (int jj = 1; jj < 16; jj++) mx = fmaxf(mx, sc[jj]);
#pragma unroll
    for (int o2 = 1; o2 < 8; o2 <<= 1) mx = fmaxf(mx, __shfl_xor_sync(0xffffffffu, mx, o2));
    float sum = 0.f;
#pragma unroll
    for (int jj = 0; jj < 16; jj++) { sc[jj] = __expf(sc[jj] - mx); sum += sc[jj]; }
#pragma unroll
    for (int o2 = 1; o2 < 8; o2 <<= 1) sum += __shfl_xor_sync(0xffffffffu, sum, o2);
    float inv = 1.f / sum;

    // store p (tf32) to smem
#pragma unroll
    for (int jj = 0; jj < 16; jj++)
        ps[qi * PSTR + g + 8 * jj] = f2tf(sc[jj] * inv);
    __syncthreads();

    // P[32x128] @ V[128x48] via m16n8k8 tf32 mma. 12 tiles (2m x 6n) over 8 warps.
    int wid = tid >> 5, lane = tid & 31;
    int group = lane >> 2, tg = lane & 3;
    int ntile_cnt = (wid < 4) ? 2 : 1;
#pragma unroll
    for (int tt = 0; tt < 2; tt++) {
        if (tt >= ntile_cnt) break;
        int t  = wid + tt * 8;        // tile id 0..11
        int m0 = (t & 1) * 16;
        int n0 = (t >> 1) * 8;
        float acc[4] = {0.f, 0.f, 0.f, 0.f};
#pragma unroll
        for (int ks8 = 0; ks8 < 16; ks8++) {
            int kb = ks8 * 8;
            uint32_t a[4];
            a[0] = ps[(m0 + group)     * PSTR + kb + tg];
            a[1] = ps[(m0 + group + 8) * PSTR + kb + tg];
            a[2] = ps[(m0 + group)     * PSTR + kb + tg + 4];
            a[3] = ps[(m0 + group + 8) * PSTR + kb + tg + 4];
            uint32_t b[2];
            b[0] = vs[(kb + tg)     * VSTR + n0 + group];
            b[1] = vs[(kb + tg + 4) * VSTR + n0 + group];
            mma8(acc, a, b);
        }
#pragma unroll
        for (int half = 0; half < 2; half++) {
            int qrow = m0 + group + half * 8;
            int col  = n0 + tg * 2;
            size_t base = (size_t)(w * 32 + qrow) * CA + h * 48 + col;
            float g0 = gate[base];
            float g1 = gate[base + 1];
            t1[base]     = f2tf(g0 * acc[half * 2 + 0]);
            t1[base + 1] = f2tf(g1 * acc[half * 2 + 1]);
        }
    }
}

// ---------------- launch ----------------
extern "C" void kernel_launch(void* const* d_in, const int* in_sizes, int n_in,
                              void* d_out, int out_size)
{
    const float* a        = (const float*)d_in[0];
    const float* s        = (const float*)d_in[1];
    const float* z        = (const float*)d_in[2];
    const float* gamma_s  = (const float*)d_in[3];
    const float* ws       = (const float*)d_in[4];
    const float* bs       = (const float*)d_in[5];
    const float* wskip    = (const float*)d_in[6];
    const float* lnzg     = (const float*)d_in[7];
    const float* wz       = (const float*)d_in[8];
    const float* wq       = (const float*)d_in[9];
    const float* bq       = (const float*)d_in[10];
    const float* wk       = (const float*)d_in[11];
    const float* wv       = (const float*)d_in[12];
    const float* wg       = (const float*)d_in[13];
    const float* bg       = (const float*)d_in[14];
    const float* wo       = (const float*)d_in[15];
    const float* bo       = (const float*)d_in[16];
    const float* wlast    = (const float*)d_in[17];
    const float* blast    = (const float*)d_in[18];
    float* out = (float*)d_out;

    float *p_sln, *p_alnr, *p_t2, *p_q, *p_k, *p_v, *p_g, *p_bias;
    uint32_t *p_stf, *p_alnt, *p_t1t, *p_wt;
    cudaGetSymbolAddress((void**)&p_sln,  g_sln);
    cudaGetSymbolAddress((void**)&p_stf,  g_stf);
    cudaGetSymbolAddress((void**)&p_alnr, g_alnr);
    cudaGetSymbolAddress((void**)&p_alnt, g_alnt);
    cudaGetSymbolAddress((void**)&p_t2,   g_t2);
    cudaGetSymbolAddress((void**)&p_q,    g_q);
    cudaGetSymbolAddress((void**)&p_k,    g_k);
    cudaGetSymbolAddress((void**)&p_v,    g_v);
    cudaGetSymbolAddress((void**)&p_g,    g_g);
    cudaGetSymbolAddress((void**)&p_t1t,  g_t1t);
    cudaGetSymbolAddress((void**)&p_bias, g_bias);
    cudaGetSymbolAddress((void**)&p_wt,   g_wt);

    cudaFuncSetAttribute(attn_kernel, cudaFuncAttributeMaxDynamicSharedMemorySize, ATTN_SMEM);
    cudaFuncSetAttribute(tgemm_ca,    cudaFuncAttributeMaxDynamicSharedMemorySize, GEMM_SMEM);
    cudaFuncSetAttribute(fat2_kernel, cudaFuncAttributeMaxDynamicSharedMemorySize, BIAS2_SMEM);

    // 0: LN(s)+stf / LN(a) / weight tf32 conversion — all independent
    ln_fused_kernel<<<4192, 256>>>(s, gamma_s, p_sln, p_stf, a, p_alnr,
                                   wq, wk, wv, wg, wo, wlast, p_wt);

    // 1: aln = sigmoid(sln@ws + bs) * ln(a) + sln@wskip  (writes tf32 aln)
    adaln_kernel<<<dim3(12, 32), 256>>>(p_sln, ws, wskip, bs, p_alnr, p_alnt);

    // 2: FAT — pair-bias (z-path) overlapped with QKVG + wlast GEMMs
    fat2_kernel<<<FATN, 256, BIAS2_SMEM>>>(z, lnzg, wz, p_bias,
                                           p_alnt, p_stf, p_wt, bq, bg, blast,
                                           p_q, p_k, p_v, p_g, p_t2);

    // 3: attention -> t1 = tf32(g * o)   (P·V on tensor cores)
    attn_kernel<<<dim3(128, 16), 256, ATTN_SMEM>>>(p_q, p_k, p_v, p_bias, p_g, p_t1t);

    // 4: out = (t1 @ wo + bo) * t2
    tgemm_ca<<<dim3(6, 32), 256, GEMM_SMEM>>>(p_t1t, p_wt + (size_t)4 * W768,
                                              bo, p_t2, out, 768, 0);
}

// round 17
// speedup vs baseline: 1.3911x; 1.0565x over previous
#include <cuda_runtime.h>
#include <math.h>
#include <stdint.h>

// Problem constants
#define N_TOK 4096
#define CA 768
#define CS 384
#define CZ 128
#define NH 16
#define HD 48

#define W768 589824     // 768*768
#define W384 294912     // 384*768

// ---------------- scratch ----------------
__device__ __align__(16) float    g_sln [N_TOK * CS];
__device__ __align__(16) uint32_t g_stf [N_TOK * CS];     // tf32(s)
__device__ __align__(16) float    g_alnr[N_TOK * CA];
__device__ __align__(16) uint32_t g_alnt[N_TOK * CA];     // tf32(aln)
__device__ __align__(16) float    g_t2  [N_TOK * CA];     // sigmoid(s@wlast+blast)
__device__ __align__(16) float    g_q   [N_TOK * CA];
__device__ __align__(16) float    g_k   [N_TOK * CA];
__device__ __align__(16) float    g_v   [N_TOK * CA];
__device__ __align__(16) float    g_g   [N_TOK * CA];
__device__ __align__(16) uint32_t g_t1t [N_TOK * CA];     // tf32(g*o)
__device__ __align__(16) float    g_bias[NH * 128 * 32 * 128];
__device__ __align__(16) uint32_t g_wt  [5 * W768 + W384]; // wq wk wv wg wo | wlast

// ---------------- TF32 helpers ----------------
__device__ __forceinline__ uint32_t f2tf(float x)
{
    uint32_t r;
    asm("cvt.rna.tf32.f32 %0, %1;" : "=r"(r) : "f"(x));
    return r;
}

__device__ __forceinline__ void mma8(float* c, const uint32_t* a, const uint32_t* b)
{
    asm volatile("mma.sync.aligned.m16n8k8.row.col.f32.tf32.tf32.f32 "
                 "{%0,%1,%2,%3}, {%4,%5,%6,%7}, {%8,%9}, {%0,%1,%2,%3};"
                 : "+f"(c[0]), "+f"(c[1]), "+f"(c[2]), "+f"(c[3])
                 : "r"(a[0]), "r"(a[1]), "r"(a[2]), "r"(a[3]),
                   "r"(b[0]), "r"(b[1]));
}

__device__ __forceinline__ void cp16(uint32_t dst, const void* src)
{
    asm volatile("cp.async.cg.shared.global [%0], [%1], 16;" :: "r"(dst), "l"(src));
}
#define CP_COMMIT() asm volatile("cp.async.commit_group;")
#define CP_WAIT1()  asm volatile("cp.async.wait_group 1;")

// ---------------- fused LN + weight-convert kernel ----------------
__global__ __launch_bounds__(256) void ln_fused_kernel(const float* __restrict__ s,
                                                       const float* __restrict__ gamma,
                                                       float* __restrict__ sln,
                                                       uint32_t* __restrict__ stf,
                                                       const float* __restrict__ a,
                                                       float* __restrict__ alnr,
                                                       const float* __restrict__ wq,
                                                       const float* __restrict__ wk,
                                                       const float* __restrict__ wv,
                                                       const float* __restrict__ wg,
                                                       const float* __restrict__ wo,
                                                       const float* __restrict__ wlast,
                                                       uint32_t* __restrict__ wt)
{
    int lane = threadIdx.x & 31;
    int bx = blockIdx.x;
    if (bx < 512) {
        int row = bx * 8 + (threadIdx.x >> 5);
        const float* x = s + (size_t)row * CS;
        float v[12];
        float sum = 0.f;
#pragma unroll
        for (int i = 0; i < 12; i++) { v[i] = x[lane + 32 * i]; sum += v[i]; }
#pragma unroll
        for (int o = 16; o; o >>= 1) sum += __shfl_xor_sync(0xffffffffu, sum, o);
        float m = sum * (1.0f / CS);
        float ss = 0.f;
#pragma unroll
        for (int i = 0; i < 12; i++) { float d = v[i] - m; ss += d * d; }
#pragma unroll
        for (int o = 16; o; o >>= 1) ss += __shfl_xor_sync(0xffffffffu, ss, o);
        float inv = rsqrtf(ss * (1.0f / CS) + 1e-5f);
        float* op = sln + (size_t)row * CS;
        uint32_t* op2 = stf + (size_t)row * CS;
#pragma unroll
        for (int i = 0; i < 12; i++) {
            op [lane + 32 * i] = (v[i] - m) * inv * gamma[lane + 32 * i];
            op2[lane + 32 * i] = f2tf(v[i]);
        }
    } else if (bx < 1024) {
        int row = (bx - 512) * 8 + (threadIdx.x >> 5);
        const float* x = a + (size_t)row * CA;
        float v[24];
        float sum = 0.f;
#pragma unroll
        for (int i = 0; i < 24; i++) { v[i] = x[lane + 32 * i]; sum += v[i]; }
#pragma unroll
        for (int o = 16; o; o >>= 1) sum += __shfl_xor_sync(0xffffffffu, sum, o);
        float m = sum * (1.0f / CA);
        float ss = 0.f;
#pragma unroll
        for (int i = 0; i < 24; i++) { float d = v[i] - m; ss += d * d; }
#pragma unroll
        for (int o = 16; o; o >>= 1) ss += __shfl_xor_sync(0xffffffffu, ss, o);
        float inv = rsqrtf(ss * (1.0f / CA) + 1e-5f);
        float* op = alnr + (size_t)row * CA;
#pragma unroll
        for (int i = 0; i < 24; i++)
            op[lane + 32 * i] = (v[i] - m) * inv;
    } else {
        int b = bx - 1024;
        const float* src;
        uint32_t* dst;
        int local;
        if (b < 2880) {
            int seg = b / 576;
            local = b - seg * 576;
            src = (seg == 0) ? wq : (seg == 1) ? wk : (seg == 2) ? wv
                : (seg == 3) ? wg : wo;
            dst = wt + (size_t)seg * W768;
        } else {
            local = b - 2880;
            src = wlast;
            dst = wt + (size_t)5 * W768;
        }
        int idx = local * 256 + threadIdx.x;
        float4 vsrc = ((const float4*)src)[idx];
        uint4 vd;
        vd.x = f2tf(vsrc.x); vd.y = f2tf(vsrc.y);
        vd.z = f2tf(vsrc.z); vd.w = f2tf(vsrc.w);
        ((uint4*)dst)[idx] = vd;
    }
}

// ---------------- cp.async TF32 GEMM: BM=128 BN=128 BK=16, 3 stages (R10) ------------
#define ASTRIDE 20
#define STAGE_WORDS (128 * ASTRIDE + 16 * 136)   // 4736
#define GEMM_SMEM (3 * STAGE_WORDS * 4)          // 56832 B

__device__ __forceinline__ void issue_tile(uint32_t sbase,
                                           const uint32_t* __restrict__ A,
                                           const uint32_t* __restrict__ B,
                                           int K, int k0, int row0, int col0, int tid)
{
    int arow = tid >> 1, ac = (tid & 1) * 2;
    const uint32_t* asrc = A + (size_t)(row0 + arow) * K + k0 + ac * 4;
    uint32_t adst = sbase + (arow * ASTRIDE + ac * 4) * 4;
    cp16(adst, asrc);
    cp16(adst + 16, asrc + 4);
    int brow = tid >> 4, bc = (tid & 15) * 2;
    const uint32_t* bsrc = B + (size_t)(k0 + brow) * 768 + col0 + bc * 4;
    uint32_t bdst = sbase + (128 * ASTRIDE + brow * 136 + bc * 4) * 4;
    cp16(bdst, bsrc);
    cp16(bdst + 16, bsrc + 4);
}

__device__ __forceinline__ void gemm_ca_body(const uint32_t* __restrict__ A,
                                             const uint32_t* __restrict__ B,
                                             const float* __restrict__ bias,
                                             const float* __restrict__ emul,
                                             float* __restrict__ C,
                                             int K, int act, int bx, int by)
{
    extern __shared__ uint32_t gsm[];
    uint32_t sbase = (uint32_t)__cvta_generic_to_shared(gsm);

    int tid = threadIdx.x;
    int wid = tid >> 5, lane = tid & 31;
    int warp_m = wid >> 2, warp_n = wid & 3;
    int group = lane >> 2, tg = lane & 3;
    int row0 = by * 128;
    int col0 = bx * 128;

    float acc[4][4][4];
#pragma unroll
    for (int mt = 0; mt < 4; mt++)
#pragma unroll
        for (int nt = 0; nt < 4; nt++)
#pragma unroll
            for (int r = 0; r < 4; r++) acc[mt][nt][r] = 0.f;

    int kt = K >> 4;
    issue_tile(sbase, A, B, K, 0, row0, col0, tid);
    CP_COMMIT();
    issue_tile(sbase + STAGE_WORDS * 4, A, B, K, 16, row0, col0, tid);
    CP_COMMIT();

    int stage = 0;
    for (int it = 0; it < kt; it++) {
        CP_WAIT1();
        __syncthreads();
        const uint32_t* As = gsm + stage * STAGE_WORDS;
        const uint32_t* Bs = As + 128 * ASTRIDE;

#pragma unroll
        for (int kc = 0; kc < 2; kc++) {
            int kb = kc * 8;
            uint32_t afr[4][4];
#pragma unroll
            for (int mt = 0; mt < 4; mt++) {
                int m = (warp_m * 64 + mt * 16 + group) * ASTRIDE;
                afr[mt][0] = As[m + kb + tg];
                afr[mt][1] = As[m + 8 * ASTRIDE + kb + tg];
                afr[mt][2] = As[m + kb + tg + 4];
                afr[mt][3] = As[m + 8 * ASTRIDE + kb + tg + 4];
            }
            uint32_t bfr[4][2];
#pragma unroll
            for (int nt = 0; nt < 4; nt++) {
                int n = warp_n * 32 + nt * 8 + group;
                bfr[nt][0] = Bs[(kb + tg) * 136 + n];
                bfr[nt][1] = Bs[(kb + tg + 4) * 136 + n];
            }
#pragma unroll
            for (int mt = 0; mt < 4; mt++)
#pragma unroll
                for (int nt = 0; nt < 4; nt++)
                    mma8(acc[mt][nt], afr[mt], bfr[nt]);
        }

        if (it + 2 < kt) {
            int nst = stage + 2; if (nst >= 3) nst -= 3;
            issue_tile(sbase + nst * STAGE_WORDS * 4, A, B, K,
                       (it + 2) * 16, row0, col0, tid);
        }
        CP_COMMIT();
        stage = stage + 1; if (stage == 3) stage = 0;
    }

#pragma unroll
    for (int mt = 0; mt < 4; mt++) {
#pragma unroll
        for (int nt = 0; nt < 4; nt++) {
            int col = col0 + warp_n * 32 + nt * 8 + tg * 2;
            float b0 = bias ? bias[col]     : 0.f;
            float b1 = bias ? bias[col + 1] : 0.f;
#pragma unroll
            for (int half = 0; half < 2; half++) {
                int row = row0 + warp_m * 64 + mt * 16 + group + half * 8;
                float v0 = acc[mt][nt][half * 2 + 0] + b0;
                float v1 = acc[mt][nt][half * 2 + 1] + b1;
                if (act == 1) {
                    v0 = 1.f / (1.f + expf(-v0));
                    v1 = 1.f / (1.f + expf(-v1));
                }
                if (emul) {
                    v0 *= emul[(size_t)row * 768 + col];
                    v1 *= emul[(size_t)row * 768 + col + 1];
                }
                float2 r = make_float2(v0, v1);
                *(float2*)&C[(size_t)row * 768 + col] = r;
            }
        }
    }
}

__global__ __launch_bounds__(256) void tgemm_ca(const uint32_t* __restrict__ A,
                                                const uint32_t* __restrict__ B,
                                                const float* __restrict__ bias,
                                                const float* __restrict__ emul,
                                                float* __restrict__ C,
                                                int K, int act)
{
    gemm_ca_body(A, B, bias, emul, C, K, act, blockIdx.x, blockIdx.y);
}

// ---------------- bias2 body (LN(z)*gamma @ wz as fused LN + TF32 GEMM) --------------
#define ZAS 132
#define ZBS 24
#define BIAS2_SMEM ((128 * ZAS + 128 * ZBS) * 4)   // 79872 B

__device__ __forceinline__ void bias2_body(int blk,
                                           const float* __restrict__ z,
                                           const float* __restrict__ gamma,
                                           const float* __restrict__ wz,
                                           float* __restrict__ out)
{
    extern __shared__ uint32_t dyn[];
    uint32_t* As = dyn;
    uint32_t* Bs = dyn + 128 * ZAS;
    float*    st = (float*)dyn;

    int tid = threadIdx.x;
    int wid = tid >> 5, lane = tid & 31;

    for (int idx = tid; idx < 2048; idx += 256) {
        int c = idx >> 4, h = idx & 15;
        Bs[c * ZBS + h] = f2tf(wz[idx]);
    }

    float4 g4 = *(const float4*)(gamma + lane * 4);

    const float* zbase = z + ((size_t)blk * 128 + wid) * CZ + lane * 4;
    float4 rv[16];
#pragma unroll
    for (int i = 0; i < 16; i++)
        rv[i] = *(const float4*)(zbase + (size_t)i * 8 * CZ);

#pragma unroll
    for (int i = 0; i < 16; i++) {
        int r = wid + 8 * i;
        float4 x = rv[i];
        float sum = x.x + x.y + x.z + x.w;
#pragma unroll
        for (int o = 16; o; o >>= 1) sum += __shfl_xor_sync(0xffffffffu, sum, o);
        float m = sum * (1.0f / CZ);
        float d0 = x.x - m, d1 = x.y - m, d2 = x.z - m, d3 = x.w - m;
        float ss = d0 * d0 + d1 * d1 + d2 * d2 + d3 * d3;
#pragma unroll
        for (int o = 16; o; o >>= 1) ss += __shfl_xor_sync(0xffffffffu, ss, o);
        float inv = rsqrtf(ss * (1.0f / CZ) + 1e-5f);
        uint4 pk;
        pk.x = f2tf(d0 * inv * g4.x);
        pk.y = f2tf(d1 * inv * g4.y);
        pk.z = f2tf(d2 * inv * g4.z);
        pk.w = f2tf(d3 * inv * g4.w);
        *(uint4*)&As[r * ZAS + lane * 4] = pk;
    }
    __syncthreads();

    int group = lane >> 2, tg = lane & 3;
    int m0 = wid * 16;
    float acc[2][4];
#pragma unroll
    for (int nt = 0; nt < 2; nt++)
#pragma unroll
        for (int r = 0; r < 4; r++) acc[nt][r] = 0.f;

#pragma unroll
    for (int ks = 0; ks < 16; ks++) {
        int kb = ks * 8;
        uint32_t a[4];
        a[0] = As[(m0 + group)     * ZAS + kb + tg];
        a[1] = As[(m0 + group + 8) * ZAS + kb + tg];
        a[2] = As[(m0 + group)     * ZAS + kb + tg + 4];
        a[3] = As[(m0 + group + 8) * ZAS + kb + tg + 4];
        uint32_t b0[2], b1[2];
        b0[0] = Bs[(kb + tg)     * ZBS + group];
        b0[1] = Bs[(kb + tg + 4) * ZBS + group];
        b1[0] = Bs[(kb + tg)     * ZBS + 8 + group];
        b1[1] = Bs[(kb + tg + 4) * ZBS + 8 + group];
        mma8(acc[0], a, b0);
        mma8(acc[1], a, b1);
    }
    __syncthreads();

#pragma unroll
    for (int nt = 0; nt < 2; nt++)
#pragma unroll
        for (int half = 0; half < 2; half++) {
            int m  = m0 + group + half * 8;
            int h0 = nt * 8 + tg * 2;
            st[h0       * 129 + m] = acc[nt][half * 2 + 0];
            st[(h0 + 1) * 129 + m] = acc[nt][half * 2 + 1];
        }
    __syncthreads();

    int wwin = blk >> 5;
    int rembase = (blk & 31) * 128;
#pragma unroll
    for (int i = 0; i < 8; i++) {
        int idx = tid + 256 * i;
        int h = idx >> 7, m = idx & 127;
        out[((size_t)(wwin * 16 + h)) * 4096 + rembase + m] = st[h * 129 + m];
    }
}

// ---------------- FAT kernel: bias2 (4096) ∥ qkvg+wlast GEMMs (960) ------------------
#define FATQ 960
#define FATN 5056
__global__ __launch_bounds__(256) void fat2_kernel(const float* __restrict__ z,
                                                   const float* __restrict__ lnzg,
                                                   const float* __restrict__ wz,
                                                   float* __restrict__ bias_out,
                                                   const uint32_t* __restrict__ alnt,
                                                   const uint32_t* __restrict__ stf,
                                                   const uint32_t* __restrict__ wt,
                                                   const float* __restrict__ bq,
                                                   const float* __restrict__ bg,
                                                   const float* __restrict__ blast,
                                                   float* __restrict__ q,
                                                   float* __restrict__ k,
                                                   float* __restrict__ v,
                                                   float* __restrict__ g,
                                                   float* __restrict__ t2)
{
    int idx = blockIdx.x;
    int q_lo = (int)(((long long)idx       * FATQ) / FATN);
    int q_hi = (int)(((long long)(idx + 1) * FATQ) / FATN);
    if (q_hi > q_lo) {
        int qid = q_lo;                 // 0..959
        int bx  = qid % 6;
        int tmp = qid / 6;
        int by  = tmp % 32;
        int zi  = tmp / 32;             // 0..4
        if (zi < 4) {
            const uint32_t* B = wt + (size_t)zi * W768;
            const float* bias = (zi == 0) ? bq : (zi == 3) ? bg : nullptr;
            float* C          = (zi == 0) ? q  : (zi == 1) ? k  : (zi == 2) ? v  : g;
            int act           = (zi == 3) ? 1 : 0;
            gemm_ca_body(alnt, B, bias, nullptr, C, 768, act, bx, by);
        } else {
            gemm_ca_body(stf, wt + (size_t)5 * W768, blast, nullptr, t2, 384, 1,
                         bx, by);
        }
    } else {
        int bid = idx - q_lo;           // 0..4095
        bias2_body(bid, z, lnzg, wz, bias_out);
    }
}

// ---------------- dual-B adaln GEMM (BN=64, writes tf32 aln) ----------------
#define AS_STRIDE 136
#define BS_STRIDE 72
__global__ __launch_bounds__(256) void adaln_kernel(const float* __restrict__ sln,
                                                    const float* __restrict__ ws,
                                                    const float* __restrict__ wskip,
                                                    const float* __restrict__ bs,
                                                    const float* __restrict__ alnr,
                                                    uint32_t* __restrict__ alnt)
{
    __shared__ uint32_t As [16 * AS_STRIDE];
    __shared__ uint32_t Bs1[16 * BS_STRIDE];
    __shared__ uint32_t Bs2[16 * BS_STRIDE];

    const int K = 384;
    int tid = threadIdx.x;
    int wid = tid >> 5, lane = tid & 31;
    int warp_m = wid >> 1, warp_n = wid & 1;
    int group = lane >> 2, tg = lane & 3;
    int row0 = blockIdx.y * 128;
    int col0 = blockIdx.x * 64;

    int arow = tid >> 1, akp = (tid & 1) * 8;
    int brow = tid >> 4, bcol = (tid & 15) * 4;

    const float* Abase = sln + (size_t)(row0 + arow) * K;

    float acc1[2][4][4], acc2[2][4][4];
#pragma unroll
    for (int mt = 0; mt < 2; mt++)
#pragma unroll
        for (int nt = 0; nt < 4; nt++)
#pragma unroll
            for (int r = 0; r < 4; r++) { acc1[mt][nt][r] = 0.f; acc2[mt][nt][r] = 0.f; }

    {
        float4 va0 = *(const float4*)(Abase + akp);
        float4 va1 = *(const float4*)(Abase + akp + 4);
        float4 vb1 = *(const float4*)(ws    + (size_t)brow * 768 + col0 + bcol);
        float4 vb2 = *(const float4*)(wskip + (size_t)brow * 768 + col0 + bcol);
        float av[8] = {va0.x, va0.y, va0.z, va0.w, va1.x, va1.y, va1.z, va1.w};
#pragma unroll
        for (int i = 0; i < 8; i++) As[(akp + i) * AS_STRIDE + arow] = f2tf(av[i]);
        float b1v[4] = {vb1.x, vb1.y, vb1.z, vb1.w};
        float b2v[4] = {vb2.x, vb2.y, vb2.z, vb2.w};
#pragma unroll
        for (int i = 0; i < 4; i++) {
            Bs1[brow * BS_STRIDE + bcol + i] = f2tf(b1v[i]);
            Bs2[brow * BS_STRIDE + bcol + i] = f2tf(b2v[i]);
        }
    }

    for (int k0 = 0; k0 < K; k0 += 16) {
        __syncthreads();
        bool has_next = (k0 + 16) < K;
        float4 va0, va1, vb1, vb2;
        if (has_next) {
            va0 = *(const float4*)(Abase + k0 + 16 + akp);
            va1 = *(const float4*)(Abase + k0 + 16 + akp + 4);
            vb1 = *(const float4*)(ws    + (size_t)(k0 + 16 + brow) * 768 + col0 + bcol);
            vb2 = *(const float4*)(wskip + (size_t)(k0 + 16 + brow) * 768 + col0 + bcol);
        }

#pragma unroll
        for (int kc = 0; kc < 2; kc++) {
            int kb = kc * 8;
            uint32_t afr[2][4];
#pragma unroll
            for (int mt = 0; mt < 2; mt++) {
                int m = warp_m * 32 + mt * 16 + group;
                afr[mt][0] = As[(kb + tg) * AS_STRIDE + m];
                afr[mt][1] = As[(kb + tg) * AS_STRIDE + m + 8];
                afr[mt][2] = As[(kb + tg + 4) * AS_STRIDE + m];
                afr[mt][3] = As[(kb + tg + 4) * AS_STRIDE + m + 8];
            }
#pragma unroll
            for (int nt = 0; nt < 4; nt++) {
                int n = warp_n * 32 + nt * 8 + group;
                uint32_t b1[2], b2[2];
                b1[0] = Bs1[(kb + tg) * BS_STRIDE + n];
                b1[1] = Bs1[(kb + tg + 4) * BS_STRIDE + n];
                b2[0] = Bs2[(kb + tg) * BS_STRIDE + n];
                b2[1] = Bs2[(kb + tg + 4) * BS_STRIDE + n];
#pragma unroll
                for (int mt = 0; mt < 2; mt++) {
                    mma8(acc1[mt][nt], afr[mt], b1);
                    mma8(acc2[mt][nt], afr[mt], b2);
                }
            }
        }

        __syncthreads();
        if (has_next) {
            float av[8] = {va0.x, va0.y, va0.z, va0.w, va1.x, va1.y, va1.z, va1.w};
#pragma unroll
            for (int i = 0; i < 8; i++) As[(akp + i) * AS_STRIDE + arow] = f2tf(av[i]);
            float b1v[4] = {vb1.x, vb1.y, vb1.z, vb1.w};
            float b2v[4] = {vb2.x, vb2.y, vb2.z, vb2.w};
#pragma unroll
            for (int i = 0; i < 4; i++) {
                Bs1[brow * BS_STRIDE + bcol + i] = f2tf(b1v[i]);
                Bs2[brow * BS_STRIDE + bcol + i] = f2tf(b2v[i]);
            }
        }
    }

#pragma unroll
    for (int mt = 0; mt < 2; mt++) {
#pragma unroll
        for (int nt = 0; nt < 4; nt++) {
            int col = col0 + warp_n * 32 + nt * 8 + tg * 2;
            float b0 = bs[col], b1 = bs[col + 1];
#pragma unroll
            for (int half = 0; half < 2; half++) {
                int row = row0 + warp_m * 32 + mt * 16 + group + half * 8;
                float s0 = 1.f / (1.f + expf(-(acc1[mt][nt][half * 2 + 0] + b0)));
                float s1 = 1.f / (1.f + expf(-(acc1[mt][nt][half * 2 + 1] + b1)));
                float r0 = s0 * alnr[(size_t)row * 768 + col]     + acc2[mt][nt][half * 2 + 0];
                float r1 = s1 * alnr[(size_t)row * 768 + col + 1] + acc2[mt][nt][half * 2 + 1];
                uint2 rr;
                rr.x = f2tf(r0);
                rr.y = f2tf(r1);
                *(uint2*)&alnt[(size_t)row * 768 + col] = rr;
            }
        }
    }
}

// ---------------- local attention: full tensor-core (QK^T and P·V on mma) ------------
// smem (words): qs[32][52] tf32 | kt[48][136] tf32 (K transposed) |
//               vs[128][56] tf32 | ss/ps[32][132] (f32 scores -> tf32 p, in place)
#define QSTR 52
#define KTSTR 136
#define VSTR 56
#define PSTR 132
#define ATTN_SMEM ((32 * QSTR + 48 * KTSTR + 128 * VSTR + 32 * PSTR) * 4)
__global__ __launch_bounds__(256) void attn_kernel(const float* __restrict__ q,
                                                   const float* __restrict__ k,
                                                   const float* __restrict__ v,
                                                   const float* __restrict__ bias,
                                                   const float* __restrict__ gate,
                                                   uint32_t* __restrict__ t1)
{
    extern __shared__ uint32_t smu[];
    uint32_t* qs = smu;
    uint32_t* kt = qs + 32 * QSTR;
    uint32_t* vs = kt + 48 * KTSTR;
    uint32_t* ps = vs + 128 * VSTR;
    float*    ss = (float*)ps;
    int w = blockIdx.x, h = blockIdx.y;
    int tid = threadIdx.x;

    // Q staging (tf32)
    {
        const float* qbase = q + (size_t)w * 32 * CA + h * 48;
#pragma unroll
        for (int it = 0; it < 2; it++) {
            int i = tid + it * 256;
            if (i < 384) {
                int r = i / 12, c = i - r * 12;
                float4 v4 = *(const float4*)(qbase + (size_t)r * CA + c * 4);
                uint4 u;
                u.x = f2tf(v4.x); u.y = f2tf(v4.y);
                u.z = f2tf(v4.z); u.w = f2tf(v4.w);
                *(uint4*)&qs[r * QSTR + c * 4] = u;
            }
        }
    }
    // K transposed staging (tf32) + V staging (tf32)
    {
        int r = tid >> 1, half = tid & 1;
        int tok = w * 32 - 48 + r;
        tok = tok < 0 ? 0 : (tok > 4095 ? 4095 : tok);
        const float4* kg = (const float4*)(k + (size_t)tok * CA + h * 48) + half * 6;
        const float4* vg = (const float4*)(v + (size_t)tok * CA + h * 48) + half * 6;
        uint32_t* vd = &vs[r * VSTR + half * 24];
#pragma unroll
        for (int j = 0; j < 6; j++) {
            float4 kv = kg[j];
            int d0 = half * 24 + j * 4;
            kt[(d0 + 0) * KTSTR + r] = f2tf(kv.x);
            kt[(d0 + 1) * KTSTR + r] = f2tf(kv.y);
            kt[(d0 + 2) * KTSTR + r] = f2tf(kv.z);
            kt[(d0 + 3) * KTSTR + r] = f2tf(kv.w);
            float4 vv = vg[j];
            uint4 u;
            u.x = f2tf(vv.x); u.y = f2tf(vv.y);
            u.z = f2tf(vv.z); u.w = f2tf(vv.w);
            *(uint4*)&vd[j * 4] = u;
        }
    }
    __syncthreads();

    int wid = tid >> 5, lane = tid & 31;
    int group = lane >> 2, tg = lane & 3;
    const float scale = 0.14433756729740643f;

    // S = Q @ K^T: 32 tiles (2m x 16n) over 8 warps, 6 k8 steps
    {
        const float* bbase = bias + ((size_t)(w * 16 + h) * 32) * 128;
#pragma unroll
        for (int tt = 0; tt < 4; tt++) {
            int t  = wid + tt * 8;        // 0..31
            int m0 = (t & 1) * 16;
            int n0 = (t >> 1) * 8;
            float acc[4] = {0.f, 0.f, 0.f, 0.f};
#pragma unroll
            for (int ks8 = 0; ks8 < 6; ks8++) {
                int kb = ks8 * 8;
                uint32_t a[4];
                a[0] = qs[(m0 + group)     * QSTR + kb + tg];
                a[1] = qs[(m0 + group + 8) * QSTR + kb + tg];
                a[2] = qs[(m0 + group)     * QSTR + kb + tg + 4];
                a[3] = qs[(m0 + group + 8) * QSTR + kb + tg + 4];
                uint32_t b[2];
                b[0] = kt[(kb + tg)     * KTSTR + n0 + group];
                b[1] = kt[(kb + tg + 4) * KTSTR + n0 + group];
                mma8(acc, a, b);
            }
            int col  = n0 + tg * 2;
            int tok0 = w * 32 - 48 + col;
            bool v0ok = (tok0 >= 0)     && (tok0 < 4096);
            bool v1ok = (tok0 + 1 >= 0) && (tok0 + 1 < 4096);
#pragma unroll
            for (int half = 0; half < 2; half++) {
                int qrow = m0 + group + half * 8;
                float b0 = bbase[qrow * 128 + col];
                float b1 = bbase[qrow * 128 + col + 1];
                ss[qrow * PSTR + col]     = v0ok ? acc[half * 2 + 0] * scale + b0 : -1e9f;
                ss[qrow * PSTR + col + 1] = v1ok ? acc[half * 2 + 1] * scale + b1 : -1e9f;
            }
        }
    }
    __syncthreads();

    // softmax per row (exact fp32 path, __expf), write tf32 p in place
    {
        int row = tid >> 3, g = tid & 7;
        float sc[16];
#pragma unroll
        for (int jj = 0; jj < 16; jj++)
            sc[jj] = ss[row * PSTR + g + 8 * jj];
        float mx = sc[0];
#pragma unroll
        for (int jj = 1; jj < 16; jj++) mx = fmaxf(mx, sc[jj]);
#pragma unroll
        for (int o2 = 1; o2 < 8; o2 <<= 1) mx = fmaxf(mx, __shfl_xor_sync(0xffffffffu, mx, o2));
        float sum = 0.f;
#pragma unroll
        for (int jj = 0; jj < 16; jj++) { sc[jj] = __expf(sc[jj] - mx); sum += sc[jj]; }
#pragma unroll
        for (int o2 = 1; o2 < 8; o2 <<= 1) sum += __shfl_xor_sync(0xffffffffu, sum, o2);
        float inv = 1.f / sum;
#pragma unroll
        for (int jj = 0; jj < 16; jj++)
            ps[row * PSTR + g + 8 * jj] = f2tf(sc[jj] * inv);
    }
    __syncthreads();

    // O = P[32x128] @ V[128x48]: 12 tiles (2m x 6n) over 8 warps
    {
        int ntile_cnt = (wid < 4) ? 2 : 1;
#pragma unroll
        for (int tt = 0; tt < 2; tt++) {
            if (tt >= ntile_cnt) break;
            int t  = wid + tt * 8;        // 0..11
            int m0 = (t & 1) * 16;
            int n0 = (t >> 1) * 8;
            float acc[4] = {0.f, 0.f, 0.f, 0.f};
#pragma unroll
            for (int ks8 = 0; ks8 < 16; ks8++) {
                int kb = ks8 * 8;
                uint32_t a[4];
                a[0] = ps[(m0 + group)     * PSTR + kb + tg];
                a[1] = ps[(m0 + group + 8) * PSTR + kb + tg];
                a[2] = ps[(m0 + group)     * PSTR + kb + tg + 4];
                a[3] = ps[(m0 + group + 8) * PSTR + kb + tg + 4];
                uint32_t b[2];
                b[0] = vs[(kb + tg)     * VSTR + n0 + group];
                b[1] = vs[(kb + tg + 4) * VSTR + n0 + group];
                mma8(acc, a, b);
            }
#pragma unroll
            for (int half = 0; half < 2; half++) {
                int qrow = m0 + group + half * 8;
                int col  = n0 + tg * 2;
                size_t base = (size_t)(w * 32 + qrow) * CA + h * 48 + col;
                float g0 = gate[base];
                float g1 = gate[base + 1];
                t1[base]     = f2tf(g0 * acc[half * 2 + 0]);
                t1[base + 1] = f2tf(g1 * acc[half * 2 + 1]);
            }
        }
    }
}

// ---------------- launch ----------------
extern "C" void kernel_launch(void* const* d_in, const int* in_sizes, int n_in,
                              void* d_out, int out_size)
{
    const float* a        = (const float*)d_in[0];
    const float* s        = (const float*)d_in[1];
    const float* z        = (const float*)d_in[2];
    const float* gamma_s  = (const float*)d_in[3];
    const float* ws       = (const float*)d_in[4];
    const float* bs       = (const float*)d_in[5];
    const float* wskip    = (const float*)d_in[6];
    const float* lnzg     = (const float*)d_in[7];
    const float* wz       = (const float*)d_in[8];
    const float* wq       = (const float*)d_in[9];
    const float* bq       = (const float*)d_in[10];
    const float* wk       = (const float*)d_in[11];
    const float* wv       = (const float*)d_in[12];
    const float* wg       = (const float*)d_in[13];
    const float* bg       = (const float*)d_in[14];
    const float* wo       = (const float*)d_in[15];
    const float* bo       = (const float*)d_in[16];
    const float* wlast    = (const float*)d_in[17];
    const float* blast    = (const float*)d_in[18];
    float* out = (float*)d_out;

    float *p_sln, *p_alnr, *p_t2, *p_q, *p_k, *p_v, *p_g, *p_bias;
    uint32_t *p_stf, *p_alnt, *p_t1t, *p_wt;
    cudaGetSymbolAddress((void**)&p_sln,  g_sln);
    cudaGetSymbolAddress((void**)&p_stf,  g_stf);
    cudaGetSymbolAddress((void**)&p_alnr, g_alnr);
    cudaGetSymbolAddress((void**)&p_alnt, g_alnt);
    cudaGetSymbolAddress((void**)&p_t2,   g_t2);
    cudaGetSymbolAddress((void**)&p_q,    g_q);
    cudaGetSymbolAddress((void**)&p_k,    g_k);
    cudaGetSymbolAddress((void**)&p_v,    g_v);
    cudaGetSymbolAddress((void**)&p_g,    g_g);
    cudaGetSymbolAddress((void**)&p_t1t,  g_t1t);
    cudaGetSymbolAddress((void**)&p_bias, g_bias);
    cudaGetSymbolAddress((void**)&p_wt,   g_wt);

    cudaFuncSetAttribute(attn_kernel, cudaFuncAttributeMaxDynamicSharedMemorySize, ATTN_SMEM);
    cudaFuncSetAttribute(tgemm_ca,    cudaFuncAttributeMaxDynamicSharedMemorySize, GEMM_SMEM);
    cudaFuncSetAttribute(fat2_kernel, cudaFuncAttributeMaxDynamicSharedMemorySize, BIAS2_SMEM);

    // 0: LN(s)+stf / LN(a) / weight tf32 conversion — all independent
    ln_fused_kernel<<<4192, 256>>>(s, gamma_s, p_sln, p_stf, a, p_alnr,
                                   wq, wk, wv, wg, wo, wlast, p_wt);

    // 1: aln = sigmoid(sln@ws + bs) * ln(a) + sln@wskip  (writes tf32 aln)
    adaln_kernel<<<dim3(12, 32), 256>>>(p_sln, ws, wskip, bs, p_alnr, p_alnt);

    // 2: FAT — pair-bias (z-path) overlapped with QKVG + wlast GEMMs
    fat2_kernel<<<FATN, 256, BIAS2_SMEM>>>(z, lnzg, wz, p_bias,
                                           p_alnt, p_stf, p_wt, bq, bg, blast,
                                           p_q, p_k, p_v, p_g, p_t2);

    // 3: attention -> t1 = tf32(g * o)   (QK^T and P·V both on tensor cores)
    attn_kernel<<<dim3(128, 16), 256, ATTN_SMEM>>>(p_q, p_k, p_v, p_bias, p_g, p_t1t);

    // 4: out = (t1 @ wo + bo) * t2
    tgemm_ca<<<dim3(6, 32), 256, GEMM_SMEM>>>(p_t1t, p_wt + (size_t)4 * W768,
                                              bo, p_t2, out, 768, 0);
}